// round 10
// baseline (speedup 1.0000x reference)
#include <cuda_runtime.h>
#include <cuda_fp16.h>
#include <math.h>
#include <stdint.h>

// Problem dimensions (fixed by the reference setup_inputs)
#define S_ROWS 4096
#define IN_K   1024
#define OUT_N  4096

// ---------------------------------------------------------------------------
// Device global scratch (no cudaMalloc allowed)
// ---------------------------------------------------------------------------
__device__ float g_y[(size_t)S_ROWS * OUT_N];                      // 64 MB
__device__ __align__(256) __half g_ah[(size_t)S_ROWS * IN_K];      // hi(x)
__device__ __align__(256) __half g_al[(size_t)S_ROWS * IN_K];      // x - hi(x)
__device__ __align__(256) __half g_bh[(size_t)OUT_N * IN_K];       // hi(W)
__device__ __align__(256) __half g_bl[(size_t)OUT_N * IN_K];       // W - hi(W)
__device__ int g_rowcnt[S_ROWS / 128];                             // block-row done counters

// ---------------------------------------------------------------------------
// Helpers
// ---------------------------------------------------------------------------
__device__ __forceinline__ uint32_t smem_to_u32(const void* p) {
    uint32_t a;
    asm("{ .reg .u64 t; cvta.to.shared.u64 t, %1; cvt.u32.u64 %0, t; }" : "=r"(a) : "l"(p));
    return a;
}
__device__ __forceinline__ void cpasync16(uint32_t saddr, const void* g) {
    asm volatile("cp.async.cg.shared.global [%0], [%1], 16;" :: "r"(saddr), "l"(g));
}
__device__ __forceinline__ void ldsm4(uint32_t* r, uint32_t addr) {
    asm volatile("ldmatrix.sync.aligned.m8n8.x4.shared.b16 {%0,%1,%2,%3}, [%4];"
        : "=r"(r[0]), "=r"(r[1]), "=r"(r[2]), "=r"(r[3]) : "r"(addr));
}
__device__ __forceinline__ void mma16816(float* d, const uint32_t* a, const uint32_t* b) {
    asm volatile("mma.sync.aligned.m16n8k16.row.col.f32.f16.f16.f32 "
        "{%0,%1,%2,%3}, {%4,%5,%6,%7}, {%8,%9}, {%0,%1,%2,%3};"
        : "+f"(d[0]), "+f"(d[1]), "+f"(d[2]), "+f"(d[3])
        : "r"(a[0]), "r"(a[1]), "r"(a[2]), "r"(a[3]), "r"(b[0]), "r"(b[1]));
}

// smem per stage: AH(8K) AL(8K) BH(8K) BL(8K); 3 stages
#define SWOFF(row, c) ((uint32_t)((row) * 64 + (((c) ^ (((row) >> 1) & 3)) << 4)))
#define STAGE_SZ 32768
#define NSTAGE 3
#define T_AH 0
#define T_AL 8192
#define T_BH 16384
#define T_BL 24576
#define GEMM_SMEM (NSTAGE * STAGE_SZ)

// ---------------------------------------------------------------------------
// NF4 LUT + decision midpoints
// ---------------------------------------------------------------------------
#define LUTVALS -1.0f, -0.6961928009986877f, -0.5250730514526367f, \
    -0.39491748809814453f, -0.28444138169288635f, -0.18477343022823334f, \
    -0.09105003625154495f, 0.0f, 0.07958029955625534f, 0.16093020141124725f, \
    0.24611230194568634f, 0.33791524171829224f, 0.44070982933044434f, \
    0.5626170039176941f, 0.8726174235343933f, 1.0f

__constant__ float c_lut[16] = { LUTVALS };
__constant__ float c_mid[15] = {
    -0.8480964004993439f,  -0.6106329262256622f,  -0.4599952697753906f,
    -0.33967943489551544f, -0.23460740596055984f, -0.13791173323988914f,
    -0.045525018125772476f, 0.03979014977812767f,  0.1202552504837513f,
     0.2035212516784668f,   0.2920137718319893f,   0.3893125355243683f,
     0.5016634166240692f,   0.7176172137260437f,   0.9363087117671967f };

// ---------------------------------------------------------------------------
// Kernel 1: split fp32 -> (hi fp16, residual fp16); also zeroes the
// block-row counters for this launch (stream-ordered before the GEMM).
// ---------------------------------------------------------------------------
#define A_F4 ((S_ROWS * IN_K) / 4)
__global__ void __launch_bounds__(256)
split_fp16(const float* __restrict__ A, const float* __restrict__ B) {
    if (blockIdx.x == 0 && threadIdx.x < S_ROWS / 128)
        g_rowcnt[threadIdx.x] = 0;
    unsigned i = blockIdx.x * 256u + threadIdx.x;
    const float4* src;
    __half2 *hi, *lo;
    unsigned idx;
    if (i < A_F4) {
        src = (const float4*)A; hi = (__half2*)g_ah; lo = (__half2*)g_al; idx = i;
    } else {
        src = (const float4*)B; hi = (__half2*)g_bh; lo = (__half2*)g_bl; idx = i - A_F4;
    }
    float4 v = src[idx];
    __half hx = __float2half_rn(v.x), hy = __float2half_rn(v.y);
    __half hz = __float2half_rn(v.z), hw = __float2half_rn(v.w);
    __half lx = __float2half_rn(v.x - __half2float(hx));
    __half ly = __float2half_rn(v.y - __half2float(hy));
    __half lz = __float2half_rn(v.z - __half2float(hz));
    __half lw = __float2half_rn(v.w - __half2float(hw));
    hi[idx * 2 + 0] = __halves2half2(hx, hy);
    hi[idx * 2 + 1] = __halves2half2(hz, hw);
    lo[idx * 2 + 0] = __halves2half2(lx, ly);
    lo[idx * 2 + 1] = __halves2half2(lz, lw);
}

// ---------------------------------------------------------------------------
// Quant helpers (identical math to R9)
// ---------------------------------------------------------------------------
#define NTH 256

__device__ __forceinline__ void ins4(float s[4], float v) {
    if (v < s[3]) {
        if (v < s[2]) {
            s[3] = s[2];
            if (v < s[1]) {
                s[2] = s[1];
                if (v < s[0]) { s[1] = s[0]; s[0] = v; }
                else          { s[1] = v; }
            } else s[2] = v;
        } else s[3] = v;
    }
}

__device__ __forceinline__ void merge4(float s[4], float b0, float b1, float b2, float b3) {
    float l0 = fminf(s[0], b3), l1 = fminf(s[1], b2);
    float l2 = fminf(s[2], b1), l3 = fminf(s[3], b0);
    float t0 = fminf(l0, l2), t2 = fmaxf(l0, l2);
    float t1 = fminf(l1, l3), t3 = fmaxf(l1, l3);
    s[0] = fminf(t0, t1); s[1] = fmaxf(t0, t1);
    s[2] = fminf(t2, t3); s[3] = fmaxf(t2, t3);
}

__device__ __forceinline__ void warp_merge4(float s[4]) {
#pragma unroll
    for (int off = 16; off >= 1; off >>= 1) {
        float b0 = __shfl_xor_sync(0xffffffffu, s[0], off);
        float b1 = __shfl_xor_sync(0xffffffffu, s[1], off);
        float b2 = __shfl_xor_sync(0xffffffffu, s[2], off);
        float b3 = __shfl_xor_sync(0xffffffffu, s[3], off);
        merge4(s, b0, b1, b2, b3);
    }
}

// ---------------------------------------------------------------------------
// Kernel 2: FUSED split-fp16 HMMA GEMM + row quantization.
// GEMM part identical to R9 (CTA 128x128, BK=32, 3-stage cp.async, 8 warps,
// warp 64x32, 2 CTAs/SM). After the y-tile is stored, the CTA signals its
// block-row counter, waits for its 31 bid-contiguous siblings (same wave),
// then quantizes its own 4 rows, reusing the pipeline smem as the row cache.
// All quant math identical to R9 -> bit-identical output.
// ---------------------------------------------------------------------------
#define BKC 32
#define NCHK (IN_K / BKC)   // 32

__device__ __forceinline__ void load_chunk(uint32_t sb, int st, int c, int bm, int bn, int tid) {
    const int k0 = c * BKC;
    const uint32_t base = sb + (uint32_t)st * STAGE_SZ;
#pragma unroll
    for (int i = 0; i < 2; i++) {
        int f = tid + i * 256;        // 0..511
        int row = f >> 2, ch = f & 3;
        uint32_t so = SWOFF(row, ch);
        size_t gA = (size_t)(bm + row) * IN_K + k0 + ch * 8;
        size_t gB = (size_t)(bn + row) * IN_K + k0 + ch * 8;
        cpasync16(base + T_AH + so, g_ah + gA);
        cpasync16(base + T_AL + so, g_al + gA);
        cpasync16(base + T_BH + so, g_bh + gB);
        cpasync16(base + T_BL + so, g_bl + gB);
    }
    asm volatile("cp.async.commit_group;" ::: "memory");
}

__global__ void __launch_bounds__(256, 2)
gemm_quant(const float* __restrict__ bias, float* __restrict__ O) {
    extern __shared__ char smem[];
    const uint32_t sb = smem_to_u32(smem);
    const int tid = threadIdx.x, lane = tid & 31, warp = tid >> 5;
    const int bm = blockIdx.y * 128, bn = blockIdx.x * 128;
    const int wm = (warp >> 2) * 64, wn = (warp & 3) * 32;

    // ---------------- GEMM phase (identical to R9) ----------------
    float acc[4][4][4];
#pragma unroll
    for (int a = 0; a < 4; a++)
#pragma unroll
        for (int b = 0; b < 4; b++)
#pragma unroll
            for (int d = 0; d < 4; d++) acc[a][b][d] = 0.0f;

    load_chunk(sb, 0, 0, bm, bn, tid);
    load_chunk(sb, 1, 1, bm, bn, tid);

    const int lrow = lane & 15, lcol = lane >> 4;

    for (int c = 0; c < NCHK; c++) {
        if (c == NCHK - 1) {
            asm volatile("cp.async.wait_group 0;" ::: "memory");
        } else {
            asm volatile("cp.async.wait_group 1;" ::: "memory");
        }
        __syncthreads();
        if (c + 2 < NCHK)
            load_chunk(sb, (c + 2) % NSTAGE, c + 2, bm, bn, tid);

        const uint32_t base = sb + (uint32_t)(c % NSTAGE) * STAGE_SZ;
#pragma unroll
        for (int ks = 0; ks < 2; ks++) {
            const int kc = ks * 2 + lcol;
            uint32_t a_h[4][4], a_l[4][4], b_h[4][2], b_l[4][2];

#pragma unroll
            for (int mf = 0; mf < 4; mf++)
                ldsm4(a_h[mf], base + T_AH + SWOFF(wm + mf * 16 + lrow, kc));
#pragma unroll
            for (int bg = 0; bg < 2; bg++) {
                uint32_t q[4];
                ldsm4(q, base + T_BH + SWOFF(wn + bg * 16 + lrow, kc));
                b_h[bg * 2 + 0][0] = q[0]; b_h[bg * 2 + 0][1] = q[2];
                b_h[bg * 2 + 1][0] = q[1]; b_h[bg * 2 + 1][1] = q[3];
            }
#pragma unroll
            for (int bg = 0; bg < 2; bg++) {
                uint32_t q[4];
                ldsm4(q, base + T_BL + SWOFF(wn + bg * 16 + lrow, kc));
                b_l[bg * 2 + 0][0] = q[0]; b_l[bg * 2 + 0][1] = q[2];
                b_l[bg * 2 + 1][0] = q[1]; b_l[bg * 2 + 1][1] = q[3];
            }
#pragma unroll
            for (int mf = 0; mf < 4; mf++)
                ldsm4(a_l[mf], base + T_AL + SWOFF(wm + mf * 16 + lrow, kc));

#pragma unroll
            for (int mf = 0; mf < 4; mf++)
#pragma unroll
                for (int nf = 0; nf < 4; nf++)
                    mma16816(acc[mf][nf], a_h[mf], b_h[nf]);
#pragma unroll
            for (int mf = 0; mf < 4; mf++)
#pragma unroll
                for (int nf = 0; nf < 4; nf++)
                    mma16816(acc[mf][nf], a_h[mf], b_l[nf]);
#pragma unroll
            for (int mf = 0; mf < 4; mf++)
#pragma unroll
                for (int nf = 0; nf < 4; nf++)
                    mma16816(acc[mf][nf], a_l[mf], b_h[nf]);
        }
    }

    const int mrow = lane >> 2, ncol = (lane & 3) * 2;
#pragma unroll
    for (int nf = 0; nf < 4; nf++) {
        const int n = bn + wn + nf * 8 + ncol;
        const float2 bv = *(const float2*)&bias[n];
#pragma unroll
        for (int mf = 0; mf < 4; mf++) {
            const int m0 = bm + wm + mf * 16 + mrow;
            float2 v0 = make_float2(acc[mf][nf][0] + bv.x, acc[mf][nf][1] + bv.y);
            float2 v1 = make_float2(acc[mf][nf][2] + bv.x, acc[mf][nf][3] + bv.y);
            *(float2*)&g_y[(size_t)m0 * OUT_N + n] = v0;
            *(float2*)&g_y[(size_t)(m0 + 8) * OUT_N + n] = v1;
        }
    }

    // ---------------- signal + wait for the block-row ----------------
    __threadfence();
    __syncthreads();
    if (tid == 0) {
        atomicAdd(&g_rowcnt[blockIdx.y], 1);
        while (atomicAdd(&g_rowcnt[blockIdx.y], 0) < (OUT_N / 128)) __nanosleep(200);
    }
    __syncthreads();
    __threadfence();

    // ---------------- quant phase: this CTA's 4 rows ----------------
    __shared__ float stage[64];
    __shared__ float pool_min[8][4], pool_max[8][4];
    __shared__ int cnt_min, cnt_max;
    __shared__ float s_t4min, s_t4max;
    __shared__ float2 s_tab[32];
    __shared__ float s_lutv[16];
    __shared__ float s_lo, s_up, s_off, s_rng, s_inv;

    // Build bucket table + LUT once
    if (tid < 32) {
        float cl = tid * 0.0625f - 1.0f;
        float cr = cl + 0.0625f;
        int base = 0; float thr = INFINITY;
#pragma unroll
        for (int i = 0; i < 15; i++) {
            float m = c_mid[i];
            if (m < cl) base++;
            else if (m < cr) thr = m;
        }
        s_tab[tid] = make_float2(thr, (float)base);
    }
    if (tid < 16) s_lutv[tid] = __half2float(__float2half_rn(c_lut[tid]));

    float* rowf = (float*)smem;              // reuse pipeline smem: 16 KB row cache
    float4* rv = (float4*)rowf;

    for (int rr = 0; rr < 4; rr++) {
        const int r = blockIdx.y * 128 + blockIdx.x * 4 + rr;
        __syncthreads();
        if (tid == 0) { cnt_min = 0; cnt_max = 0; }

        const float4* yv = (const float4*)(g_y + (size_t)r * OUT_N);

        // Pass 1: cache row, per-thread min/max
        float mn = INFINITY, mx = -INFINITY;
#pragma unroll
        for (int i = 0; i < OUT_N / 4 / NTH; i++) {
            int idx = tid + i * NTH;
            float4 v = yv[idx];
            rv[idx] = v;
            mn = fminf(mn, fminf(fminf(v.x, v.y), fminf(v.z, v.w)));
            mx = fmaxf(mx, fmaxf(fmaxf(v.x, v.y), fmaxf(v.z, v.w)));
        }

        {
            float s[4] = { mn, INFINITY, INFINITY, INFINITY };
            float g[4] = { -mx, INFINITY, INFINITY, INFINITY };
            warp_merge4(s);
            warp_merge4(g);
            if (lane == 0) {
#pragma unroll
                for (int j = 0; j < 4; j++) { stage[warp * 4 + j] = s[j]; stage[32 + warp * 4 + j] = g[j]; }
            }
        }
        __syncthreads();
        if (warp == 0) {
            float ss[4], gg[4];
            if (lane < 8) {
#pragma unroll
                for (int j = 0; j < 4; j++) { ss[j] = stage[lane * 4 + j]; gg[j] = stage[32 + lane * 4 + j]; }
            } else {
#pragma unroll
                for (int j = 0; j < 4; j++) { ss[j] = INFINITY; gg[j] = INFINITY; }
            }
            warp_merge4(ss);
            warp_merge4(gg);
            if (lane == 0) { s_t4min = ss[3]; s_t4max = gg[3]; }
        }
        __syncthreads();

        // Detect & repair: exact bottom-4 / top-4
        if (mn <= s_t4min) {
            int rank = atomicAdd(&cnt_min, 1);
            if (rank < 8) {
                float loc[4] = { INFINITY, INFINITY, INFINITY, INFINITY };
#pragma unroll
                for (int i = 0; i < OUT_N / 4 / NTH; i++) {
                    float4 v = rv[tid + i * NTH];
                    ins4(loc, v.x); ins4(loc, v.y); ins4(loc, v.z); ins4(loc, v.w);
                }
#pragma unroll
                for (int j = 0; j < 4; j++) pool_min[rank][j] = loc[j];
            }
        }
        if (-mx <= s_t4max) {
            int rank = atomicAdd(&cnt_max, 1);
            if (rank < 8) {
                float loc[4] = { INFINITY, INFINITY, INFINITY, INFINITY };
#pragma unroll
                for (int i = 0; i < OUT_N / 4 / NTH; i++) {
                    float4 v = rv[tid + i * NTH];
                    ins4(loc, -v.x); ins4(loc, -v.y); ins4(loc, -v.z); ins4(loc, -v.w);
                }
#pragma unroll
                for (int j = 0; j < 4; j++) pool_max[rank][j] = loc[j];
            }
        }
        __syncthreads();

        if (tid == 0) {
            float b[4] = { INFINITY, INFINITY, INFINITY, INFINITY };
            float t[4] = { INFINITY, INFINITY, INFINITY, INFINITY };
            int nm = cnt_min < 8 ? cnt_min : 8;
            int nM = cnt_max < 8 ? cnt_max : 8;
            for (int p = 0; p < nm; p++)
                for (int j = 0; j < 4; j++) ins4(b, pool_min[p][j]);
            for (int p = 0; p < nM; p++)
                for (int j = 0; j < 4; j++) ins4(t, pool_max[p][j]);
            // quantile positions: 2.0475 and 4092.9525
            float lo = b[2] + 0.0475f * (b[3] - b[2]);
            float h_lo = -t[3];                    // sorted[4092]
            float h_hi = -t[2];                    // sorted[4093]
            float up = h_lo + 0.9525f * (h_hi - h_lo);
            s_lo = lo; s_up = up;
            float m = b[3], M = h_lo;              // inlier extrema
            s_off = (M + m) * 0.5f;
            s_rng = (M - m) * 0.5f;
            s_inv = 1.0f / s_rng;
        }
        __syncthreads();
        const float lo = s_lo, up = s_up;
        const float offv = s_off, rng = s_rng, inv = s_inv;

        // Pass 2: quantize via bucket table and write
        float4* ov = (float4*)(O + (size_t)r * OUT_N);
#pragma unroll
        for (int i = 0; i < OUT_N / 4 / NTH; i++) {
            int idx = tid + i * NTH;
            float4 v = rv[idx];
            float o[4];
            float in[4] = { v.x, v.y, v.z, v.w };
#pragma unroll
            for (int j = 0; j < 4; j++) {
                float y  = in[j];
                float yc = y - offv;
                float base;
                if (y <= lo || y >= up) {
                    base = yc;
                } else {
                    float sc = yc * inv;
                    int cell = (int)fmaf(sc, 16.0f, 16.0f);
                    cell = cell < 0 ? 0 : (cell > 31 ? 31 : cell);
                    float2 t = s_tab[cell];
                    int q = (int)t.y + (sc > t.x ? 1 : 0);
                    base = s_lutv[q] * rng;
                }
                float outv = base + offv;
                if (!isfinite(outv)) outv = 0.0f;
                o[j] = outv;
            }
            ov[idx] = make_float4(o[0], o[1], o[2], o[3]);
        }
    }
}

// ---------------------------------------------------------------------------
// Launch
// ---------------------------------------------------------------------------
extern "C" void kernel_launch(void* const* d_in, const int* in_sizes, int n_in,
                              void* d_out, int out_size) {
    (void)in_sizes; (void)n_in; (void)out_size;
    const float* x    = (const float*)d_in[0];   // [4096, 1024]
    const float* W    = (const float*)d_in[1];   // [4096, 1024]
    const float* bias = (const float*)d_in[2];   // [4096]
    float* out = (float*)d_out;                  // [4096, 4096]

    cudaFuncSetAttribute(gemm_quant, cudaFuncAttributeMaxDynamicSharedMemorySize, GEMM_SMEM);

    split_fp16<<<(2 * A_F4) / 256, 256>>>(x, W);
    dim3 grid(OUT_N / 128, S_ROWS / 128);        // (32, 32)
    gemm_quant<<<grid, 256, GEMM_SMEM>>>(bias, out);
}

// round 11
// speedup vs baseline: 1.3167x; 1.3167x over previous
#include <cuda_runtime.h>
#include <cuda_fp16.h>
#include <math.h>
#include <stdint.h>

// Problem dimensions (fixed by the reference setup_inputs)
#define S_ROWS 4096
#define IN_K   1024
#define OUT_N  4096

// ---------------------------------------------------------------------------
// Device global scratch (no cudaMalloc allowed)
// ---------------------------------------------------------------------------
__device__ float g_y[(size_t)S_ROWS * OUT_N];                      // 64 MB
__device__ __align__(256) __half g_ah[(size_t)S_ROWS * IN_K];      // hi(x)
__device__ __align__(256) __half g_al[(size_t)S_ROWS * IN_K];      // x - hi(x)
__device__ __align__(256) __half g_bh[(size_t)OUT_N * IN_K];       // hi(W)
__device__ __align__(256) __half g_bl[(size_t)OUT_N * IN_K];       // W - hi(W)

// ---------------------------------------------------------------------------
// Helpers
// ---------------------------------------------------------------------------
__device__ __forceinline__ uint32_t smem_to_u32(const void* p) {
    uint32_t a;
    asm("{ .reg .u64 t; cvta.to.shared.u64 t, %1; cvt.u32.u64 %0, t; }" : "=r"(a) : "l"(p));
    return a;
}
__device__ __forceinline__ void cpasync16(uint32_t saddr, const void* g) {
    asm volatile("cp.async.cg.shared.global [%0], [%1], 16;" :: "r"(saddr), "l"(g));
}
__device__ __forceinline__ void ldsm4(uint32_t* r, uint32_t addr) {
    asm volatile("ldmatrix.sync.aligned.m8n8.x4.shared.b16 {%0,%1,%2,%3}, [%4];"
        : "=r"(r[0]), "=r"(r[1]), "=r"(r[2]), "=r"(r[3]) : "r"(addr));
}
__device__ __forceinline__ void mma16816(float* d, const uint32_t* a, const uint32_t* b) {
    asm volatile("mma.sync.aligned.m16n8k16.row.col.f32.f16.f16.f32 "
        "{%0,%1,%2,%3}, {%4,%5,%6,%7}, {%8,%9}, {%0,%1,%2,%3};"
        : "+f"(d[0]), "+f"(d[1]), "+f"(d[2]), "+f"(d[3])
        : "r"(a[0]), "r"(a[1]), "r"(a[2]), "r"(a[3]), "r"(b[0]), "r"(b[1]));
}

// smem per stage: AH(8K) AL(8K) BH(8K) BL(8K); 3 stages
#define SWOFF(row, c) ((uint32_t)((row) * 64 + (((c) ^ (((row) >> 1) & 3)) << 4)))
#define STAGE_SZ 32768
#define NSTAGE 3
#define T_AH 0
#define T_AL 8192
#define T_BH 16384
#define T_BL 24576
#define GEMM_SMEM (NSTAGE * STAGE_SZ)

// ---------------------------------------------------------------------------
// NF4 LUT + decision midpoints
// ---------------------------------------------------------------------------
#define LUTVALS -1.0f, -0.6961928009986877f, -0.5250730514526367f, \
    -0.39491748809814453f, -0.28444138169288635f, -0.18477343022823334f, \
    -0.09105003625154495f, 0.0f, 0.07958029955625534f, 0.16093020141124725f, \
    0.24611230194568634f, 0.33791524171829224f, 0.44070982933044434f, \
    0.5626170039176941f, 0.8726174235343933f, 1.0f

__constant__ float c_lut[16] = { LUTVALS };
__constant__ float c_mid[15] = {
    -0.8480964004993439f,  -0.6106329262256622f,  -0.4599952697753906f,
    -0.33967943489551544f, -0.23460740596055984f, -0.13791173323988914f,
    -0.045525018125772476f, 0.03979014977812767f,  0.1202552504837513f,
     0.2035212516784668f,   0.2920137718319893f,   0.3893125355243683f,
     0.5016634166240692f,   0.7176172137260437f,   0.9363087117671967f };

// ---------------------------------------------------------------------------
// Kernel 1: split fp32 -> (hi fp16, residual fp16)
// ---------------------------------------------------------------------------
#define A_F4 ((S_ROWS * IN_K) / 4)
__global__ void __launch_bounds__(256)
split_fp16(const float* __restrict__ A, const float* __restrict__ B) {
    unsigned i = blockIdx.x * 256u + threadIdx.x;
    const float4* src;
    __half2 *hi, *lo;
    unsigned idx;
    if (i < A_F4) {
        src = (const float4*)A; hi = (__half2*)g_ah; lo = (__half2*)g_al; idx = i;
    } else {
        src = (const float4*)B; hi = (__half2*)g_bh; lo = (__half2*)g_bl; idx = i - A_F4;
    }
    float4 v = src[idx];
    __half hx = __float2half_rn(v.x), hy = __float2half_rn(v.y);
    __half hz = __float2half_rn(v.z), hw = __float2half_rn(v.w);
    __half lx = __float2half_rn(v.x - __half2float(hx));
    __half ly = __float2half_rn(v.y - __half2float(hy));
    __half lz = __float2half_rn(v.z - __half2float(hz));
    __half lw = __float2half_rn(v.w - __half2float(hw));
    hi[idx * 2 + 0] = __halves2half2(hx, hy);
    hi[idx * 2 + 1] = __halves2half2(hz, hw);
    lo[idx * 2 + 0] = __halves2half2(lx, ly);
    lo[idx * 2 + 1] = __halves2half2(lz, lw);
}

// ---------------------------------------------------------------------------
// Kernel 2: split-fp16 HMMA GEMM (R9 math, chunked over block-rows)
// ---------------------------------------------------------------------------
#define BKC 32
#define NCHK (IN_K / BKC)   // 32

__device__ __forceinline__ void load_chunk(uint32_t sb, int st, int c, int bm, int bn, int tid) {
    const int k0 = c * BKC;
    const uint32_t base = sb + (uint32_t)st * STAGE_SZ;
#pragma unroll
    for (int i = 0; i < 2; i++) {
        int f = tid + i * 256;        // 0..511
        int row = f >> 2, ch = f & 3;
        uint32_t so = SWOFF(row, ch);
        size_t gA = (size_t)(bm + row) * IN_K + k0 + ch * 8;
        size_t gB = (size_t)(bn + row) * IN_K + k0 + ch * 8;
        cpasync16(base + T_AH + so, g_ah + gA);
        cpasync16(base + T_AL + so, g_al + gA);
        cpasync16(base + T_BH + so, g_bh + gB);
        cpasync16(base + T_BL + so, g_bl + gB);
    }
    asm volatile("cp.async.commit_group;" ::: "memory");
}

__global__ void __launch_bounds__(256, 2)
gemm_hmma(const float* __restrict__ bias, int bmoff) {
    extern __shared__ char smem[];
    const uint32_t sb = smem_to_u32(smem);
    const int tid = threadIdx.x, lane = tid & 31, warp = tid >> 5;
    const int bm = (blockIdx.y + bmoff) * 128, bn = blockIdx.x * 128;
    const int wm = (warp >> 2) * 64, wn = (warp & 3) * 32;

    float acc[4][4][4];
#pragma unroll
    for (int a = 0; a < 4; a++)
#pragma unroll
        for (int b = 0; b < 4; b++)
#pragma unroll
            for (int d = 0; d < 4; d++) acc[a][b][d] = 0.0f;

    load_chunk(sb, 0, 0, bm, bn, tid);
    load_chunk(sb, 1, 1, bm, bn, tid);

    const int lrow = lane & 15, lcol = lane >> 4;

    for (int c = 0; c < NCHK; c++) {
        if (c == NCHK - 1) {
            asm volatile("cp.async.wait_group 0;" ::: "memory");
        } else {
            asm volatile("cp.async.wait_group 1;" ::: "memory");
        }
        __syncthreads();
        if (c + 2 < NCHK)
            load_chunk(sb, (c + 2) % NSTAGE, c + 2, bm, bn, tid);

        const uint32_t base = sb + (uint32_t)(c % NSTAGE) * STAGE_SZ;
#pragma unroll
        for (int ks = 0; ks < 2; ks++) {
            const int kc = ks * 2 + lcol;
            uint32_t a_h[4][4], a_l[4][4], b_h[4][2], b_l[4][2];

#pragma unroll
            for (int mf = 0; mf < 4; mf++)
                ldsm4(a_h[mf], base + T_AH + SWOFF(wm + mf * 16 + lrow, kc));
#pragma unroll
            for (int bg = 0; bg < 2; bg++) {
                uint32_t q[4];
                ldsm4(q, base + T_BH + SWOFF(wn + bg * 16 + lrow, kc));
                b_h[bg * 2 + 0][0] = q[0]; b_h[bg * 2 + 0][1] = q[2];
                b_h[bg * 2 + 1][0] = q[1]; b_h[bg * 2 + 1][1] = q[3];
            }
#pragma unroll
            for (int bg = 0; bg < 2; bg++) {
                uint32_t q[4];
                ldsm4(q, base + T_BL + SWOFF(wn + bg * 16 + lrow, kc));
                b_l[bg * 2 + 0][0] = q[0]; b_l[bg * 2 + 0][1] = q[2];
                b_l[bg * 2 + 1][0] = q[1]; b_l[bg * 2 + 1][1] = q[3];
            }
#pragma unroll
            for (int mf = 0; mf < 4; mf++)
                ldsm4(a_l[mf], base + T_AL + SWOFF(wm + mf * 16 + lrow, kc));

#pragma unroll
            for (int mf = 0; mf < 4; mf++)
#pragma unroll
                for (int nf = 0; nf < 4; nf++)
                    mma16816(acc[mf][nf], a_h[mf], b_h[nf]);
#pragma unroll
            for (int mf = 0; mf < 4; mf++)
#pragma unroll
                for (int nf = 0; nf < 4; nf++)
                    mma16816(acc[mf][nf], a_h[mf], b_l[nf]);
#pragma unroll
            for (int mf = 0; mf < 4; mf++)
#pragma unroll
                for (int nf = 0; nf < 4; nf++)
                    mma16816(acc[mf][nf], a_l[mf], b_h[nf]);
        }
    }

    const int mrow = lane >> 2, ncol = (lane & 3) * 2;
#pragma unroll
    for (int nf = 0; nf < 4; nf++) {
        const int n = bn + wn + nf * 8 + ncol;
        const float2 bv = *(const float2*)&bias[n];
#pragma unroll
        for (int mf = 0; mf < 4; mf++) {
            const int m0 = bm + wm + mf * 16 + mrow;
            float2 v0 = make_float2(acc[mf][nf][0] + bv.x, acc[mf][nf][1] + bv.y);
            float2 v1 = make_float2(acc[mf][nf][2] + bv.x, acc[mf][nf][3] + bv.y);
            *(float2*)&g_y[(size_t)m0 * OUT_N + n] = v0;
            *(float2*)&g_y[(size_t)(m0 + 8) * OUT_N + n] = v1;
        }
    }
}

// ---------------------------------------------------------------------------
// Kernel 3: row statistics + NF4 quantization (R9 math, chunked)
// ---------------------------------------------------------------------------
#define NTH 256

__device__ __forceinline__ void ins4(float s[4], float v) {
    if (v < s[3]) {
        if (v < s[2]) {
            s[3] = s[2];
            if (v < s[1]) {
                s[2] = s[1];
                if (v < s[0]) { s[1] = s[0]; s[0] = v; }
                else          { s[1] = v; }
            } else s[2] = v;
        } else s[3] = v;
    }
}

__device__ __forceinline__ void merge4(float s[4], float b0, float b1, float b2, float b3) {
    float l0 = fminf(s[0], b3), l1 = fminf(s[1], b2);
    float l2 = fminf(s[2], b1), l3 = fminf(s[3], b0);
    float t0 = fminf(l0, l2), t2 = fmaxf(l0, l2);
    float t1 = fminf(l1, l3), t3 = fmaxf(l1, l3);
    s[0] = fminf(t0, t1); s[1] = fmaxf(t0, t1);
    s[2] = fminf(t2, t3); s[3] = fmaxf(t2, t3);
}

__device__ __forceinline__ void warp_merge4(float s[4]) {
#pragma unroll
    for (int off = 16; off >= 1; off >>= 1) {
        float b0 = __shfl_xor_sync(0xffffffffu, s[0], off);
        float b1 = __shfl_xor_sync(0xffffffffu, s[1], off);
        float b2 = __shfl_xor_sync(0xffffffffu, s[2], off);
        float b3 = __shfl_xor_sync(0xffffffffu, s[3], off);
        merge4(s, b0, b1, b2, b3);
    }
}

__global__ void __launch_bounds__(NTH)
row_quant(float* __restrict__ O, int roff) {
    __shared__ float row[OUT_N];
    __shared__ float stage[64];
    __shared__ float pool_min[8][4], pool_max[8][4];
    __shared__ int cnt_min, cnt_max;
    __shared__ float s_t4min, s_t4max;
    __shared__ float2 s_tab[32];
    __shared__ float s_lutv[16];
    __shared__ float s_lo, s_up, s_off, s_rng, s_inv;

    const int r    = blockIdx.x + roff;
    const int tid  = threadIdx.x;
    const int lane = tid & 31;
    const int warp = tid >> 5;

    if (tid < 32) {
        float cl = tid * 0.0625f - 1.0f;
        float cr = cl + 0.0625f;
        int base = 0; float thr = INFINITY;
#pragma unroll
        for (int i = 0; i < 15; i++) {
            float m = c_mid[i];
            if (m < cl) base++;
            else if (m < cr) thr = m;
        }
        s_tab[tid] = make_float2(thr, (float)base);
    }
    if (tid < 16) s_lutv[tid] = __half2float(__float2half_rn(c_lut[tid]));
    if (tid == 0) { cnt_min = 0; cnt_max = 0; }

    const float4* yv = reinterpret_cast<const float4*>(g_y + (size_t)r * OUT_N);
    float4* rv = reinterpret_cast<float4*>(row);

    float mn = INFINITY, mx = -INFINITY;
#pragma unroll
    for (int i = 0; i < OUT_N / 4 / NTH; i++) {
        int idx = tid + i * NTH;
        float4 v = yv[idx];
        rv[idx] = v;
        mn = fminf(mn, fminf(fminf(v.x, v.y), fminf(v.z, v.w)));
        mx = fmaxf(mx, fmaxf(fmaxf(v.x, v.y), fmaxf(v.z, v.w)));
    }

    {
        float s[4] = { mn, INFINITY, INFINITY, INFINITY };
        float g[4] = { -mx, INFINITY, INFINITY, INFINITY };
        warp_merge4(s);
        warp_merge4(g);
        if (lane == 0) {
#pragma unroll
            for (int j = 0; j < 4; j++) { stage[warp * 4 + j] = s[j]; stage[32 + warp * 4 + j] = g[j]; }
        }
    }
    __syncthreads();
    if (warp == 0) {
        float ss[4], gg[4];
        if (lane < 8) {
#pragma unroll
            for (int j = 0; j < 4; j++) { ss[j] = stage[lane * 4 + j]; gg[j] = stage[32 + lane * 4 + j]; }
        } else {
#pragma unroll
            for (int j = 0; j < 4; j++) { ss[j] = INFINITY; gg[j] = INFINITY; }
        }
        warp_merge4(ss);
        warp_merge4(gg);
        if (lane == 0) { s_t4min = ss[3]; s_t4max = gg[3]; }
    }
    __syncthreads();

    if (mn <= s_t4min) {
        int rank = atomicAdd(&cnt_min, 1);
        if (rank < 8) {
            float loc[4] = { INFINITY, INFINITY, INFINITY, INFINITY };
#pragma unroll
            for (int i = 0; i < OUT_N / 4 / NTH; i++) {
                float4 v = rv[tid + i * NTH];
                ins4(loc, v.x); ins4(loc, v.y); ins4(loc, v.z); ins4(loc, v.w);
            }
#pragma unroll
            for (int j = 0; j < 4; j++) pool_min[rank][j] = loc[j];
        }
    }
    if (-mx <= s_t4max) {
        int rank = atomicAdd(&cnt_max, 1);
        if (rank < 8) {
            float loc[4] = { INFINITY, INFINITY, INFINITY, INFINITY };
#pragma unroll
            for (int i = 0; i < OUT_N / 4 / NTH; i++) {
                float4 v = rv[tid + i * NTH];
                ins4(loc, -v.x); ins4(loc, -v.y); ins4(loc, -v.z); ins4(loc, -v.w);
            }
#pragma unroll
            for (int j = 0; j < 4; j++) pool_max[rank][j] = loc[j];
        }
    }
    __syncthreads();

    if (tid == 0) {
        float b[4] = { INFINITY, INFINITY, INFINITY, INFINITY };
        float t[4] = { INFINITY, INFINITY, INFINITY, INFINITY };
        int nm = cnt_min < 8 ? cnt_min : 8;
        int nM = cnt_max < 8 ? cnt_max : 8;
        for (int p = 0; p < nm; p++)
            for (int j = 0; j < 4; j++) ins4(b, pool_min[p][j]);
        for (int p = 0; p < nM; p++)
            for (int j = 0; j < 4; j++) ins4(t, pool_max[p][j]);
        float lo = b[2] + 0.0475f * (b[3] - b[2]);
        float h_lo = -t[3];                    // sorted[4092]
        float h_hi = -t[2];                    // sorted[4093]
        float up = h_lo + 0.9525f * (h_hi - h_lo);
        s_lo = lo; s_up = up;
        float m = b[3], M = h_lo;              // inlier extrema
        s_off = (M + m) * 0.5f;
        s_rng = (M - m) * 0.5f;
        s_inv = 1.0f / s_rng;
    }
    __syncthreads();
    const float lo = s_lo, up = s_up;
    const float offv = s_off, rng = s_rng, inv = s_inv;

    float4* ov = reinterpret_cast<float4*>(O + (size_t)r * OUT_N);
#pragma unroll
    for (int i = 0; i < OUT_N / 4 / NTH; i++) {
        int idx = tid + i * NTH;
        float4 v = rv[idx];
        float o[4];
        float in[4] = { v.x, v.y, v.z, v.w };
#pragma unroll
        for (int j = 0; j < 4; j++) {
            float y  = in[j];
            float yc = y - offv;
            float base;
            if (y <= lo || y >= up) {
                base = yc;
            } else {
                float sc = yc * inv;
                int cell = (int)fmaf(sc, 16.0f, 16.0f);
                cell = cell < 0 ? 0 : (cell > 31 ? 31 : cell);
                float2 t = s_tab[cell];
                int q = (int)t.y + (sc > t.x ? 1 : 0);
                base = s_lutv[q] * rng;
            }
            float outv = base + offv;
            if (!isfinite(outv)) outv = 0.0f;
            o[j] = outv;
        }
        ov[idx] = make_float4(o[0], o[1], o[2], o[3]);
    }
}

// ---------------------------------------------------------------------------
// Launch: chunked pipeline across two streams (capture-legal fork/join).
// Default stream: split, G0..G3 (tensor-bound, back-to-back).
// Side stream:    Q_i after event(G_i) — memory-bound quant fills idle slots.
// ---------------------------------------------------------------------------
#define NROWCHUNK 4
#define ROWS_PER_CHUNK (S_ROWS / NROWCHUNK)      // 1024

extern "C" void kernel_launch(void* const* d_in, const int* in_sizes, int n_in,
                              void* d_out, int out_size) {
    (void)in_sizes; (void)n_in; (void)out_size;
    const float* x    = (const float*)d_in[0];   // [4096, 1024]
    const float* W    = (const float*)d_in[1];   // [4096, 1024]
    const float* bias = (const float*)d_in[2];   // [4096]
    float* out = (float*)d_out;                  // [4096, 4096]

    cudaFuncSetAttribute(gemm_hmma, cudaFuncAttributeMaxDynamicSharedMemorySize, GEMM_SMEM);

    cudaStream_t s2;
    cudaStreamCreateWithFlags(&s2, cudaStreamNonBlocking);
    cudaEvent_t evG[NROWCHUNK], evQ;
    for (int i = 0; i < NROWCHUNK; i++)
        cudaEventCreateWithFlags(&evG[i], cudaEventDisableTiming);
    cudaEventCreateWithFlags(&evQ, cudaEventDisableTiming);

    split_fp16<<<(2 * A_F4) / 256, 256>>>(x, W);

    dim3 ggrid(OUT_N / 128, ROWS_PER_CHUNK / 128);   // (32, 8) per chunk
    for (int i = 0; i < NROWCHUNK; i++) {
        gemm_hmma<<<ggrid, 256, GEMM_SMEM>>>(bias, i * (ROWS_PER_CHUNK / 128));
        cudaEventRecord(evG[i], 0);
        cudaStreamWaitEvent(s2, evG[i], 0);
        row_quant<<<ROWS_PER_CHUNK, NTH, 0, s2>>>(out, i * ROWS_PER_CHUNK);
    }
    cudaEventRecord(evQ, s2);
    cudaStreamWaitEvent(0, evQ, 0);
    // streams/events intentionally not destroyed: they may be referenced by
    // an in-progress graph capture; a handful of handles leak per process.
}

// round 12
// speedup vs baseline: 1.5619x; 1.1863x over previous
#include <cuda_runtime.h>
#include <cuda_fp16.h>
#include <math.h>
#include <stdint.h>

// Problem dimensions (fixed by the reference setup_inputs)
#define S_ROWS 4096
#define IN_K   1024
#define OUT_N  4096

// ---------------------------------------------------------------------------
// Device global scratch (no cudaMalloc allowed)
// ---------------------------------------------------------------------------
__device__ float g_y[(size_t)S_ROWS * OUT_N];                      // 64 MB
__device__ __align__(256) __half g_ah[(size_t)S_ROWS * IN_K];      // hi(x)
__device__ __align__(256) __half g_al[(size_t)S_ROWS * IN_K];      // x - hi(x)
__device__ __align__(256) __half g_bh[(size_t)OUT_N * IN_K];       // hi(W)
__device__ __align__(256) __half g_bl[(size_t)OUT_N * IN_K];       // W - hi(W)

// ---------------------------------------------------------------------------
// Helpers
// ---------------------------------------------------------------------------
__device__ __forceinline__ uint32_t smem_to_u32(const void* p) {
    uint32_t a;
    asm("{ .reg .u64 t; cvta.to.shared.u64 t, %1; cvt.u32.u64 %0, t; }" : "=r"(a) : "l"(p));
    return a;
}
__device__ __forceinline__ void cpasync16(uint32_t saddr, const void* g) {
    asm volatile("cp.async.cg.shared.global [%0], [%1], 16;" :: "r"(saddr), "l"(g));
}
__device__ __forceinline__ void ldsm4(uint32_t* r, uint32_t addr) {
    asm volatile("ldmatrix.sync.aligned.m8n8.x4.shared.b16 {%0,%1,%2,%3}, [%4];"
        : "=r"(r[0]), "=r"(r[1]), "=r"(r[2]), "=r"(r[3]) : "r"(addr));
}
__device__ __forceinline__ void mma16816(float* d, const uint32_t* a, const uint32_t* b) {
    asm volatile("mma.sync.aligned.m16n8k16.row.col.f32.f16.f16.f32 "
        "{%0,%1,%2,%3}, {%4,%5,%6,%7}, {%8,%9}, {%0,%1,%2,%3};"
        : "+f"(d[0]), "+f"(d[1]), "+f"(d[2]), "+f"(d[3])
        : "r"(a[0]), "r"(a[1]), "r"(a[2]), "r"(a[3]), "r"(b[0]), "r"(b[1]));
}

// smem per stage: AH(8K) AL(8K) BH(8K) BL(8K); 3 stages
#define SWOFF(row, c) ((uint32_t)((row) * 64 + (((c) ^ (((row) >> 1) & 3)) << 4)))
#define STAGE_SZ 32768
#define NSTAGE 3
#define T_AH 0
#define T_AL 8192
#define T_BH 16384
#define T_BL 24576
#define GEMM_SMEM (NSTAGE * STAGE_SZ)

// ---------------------------------------------------------------------------
// NF4 LUT + decision midpoints
// ---------------------------------------------------------------------------
#define LUTVALS -1.0f, -0.6961928009986877f, -0.5250730514526367f, \
    -0.39491748809814453f, -0.28444138169288635f, -0.18477343022823334f, \
    -0.09105003625154495f, 0.0f, 0.07958029955625534f, 0.16093020141124725f, \
    0.24611230194568634f, 0.33791524171829224f, 0.44070982933044434f, \
    0.5626170039176941f, 0.8726174235343933f, 1.0f

__constant__ float c_lut[16] = { LUTVALS };
__constant__ float c_mid[15] = {
    -0.8480964004993439f,  -0.6106329262256622f,  -0.4599952697753906f,
    -0.33967943489551544f, -0.23460740596055984f, -0.13791173323988914f,
    -0.045525018125772476f, 0.03979014977812767f,  0.1202552504837513f,
     0.2035212516784668f,   0.2920137718319893f,   0.3893125355243683f,
     0.5016634166240692f,   0.7176172137260437f,   0.9363087117671967f };

// ---------------------------------------------------------------------------
// Kernel 1: split fp32 -> (hi fp16, residual fp16)
// ---------------------------------------------------------------------------
#define A_F4 ((S_ROWS * IN_K) / 4)
__global__ void __launch_bounds__(256)
split_fp16(const float* __restrict__ A, const float* __restrict__ B) {
    unsigned i = blockIdx.x * 256u + threadIdx.x;
    const float4* src;
    __half2 *hi, *lo;
    unsigned idx;
    if (i < A_F4) {
        src = (const float4*)A; hi = (__half2*)g_ah; lo = (__half2*)g_al; idx = i;
    } else {
        src = (const float4*)B; hi = (__half2*)g_bh; lo = (__half2*)g_bl; idx = i - A_F4;
    }
    float4 v = src[idx];
    __half hx = __float2half_rn(v.x), hy = __float2half_rn(v.y);
    __half hz = __float2half_rn(v.z), hw = __float2half_rn(v.w);
    __half lx = __float2half_rn(v.x - __half2float(hx));
    __half ly = __float2half_rn(v.y - __half2float(hy));
    __half lz = __float2half_rn(v.z - __half2float(hz));
    __half lw = __float2half_rn(v.w - __half2float(hw));
    hi[idx * 2 + 0] = __halves2half2(hx, hy);
    hi[idx * 2 + 1] = __halves2half2(hz, hw);
    lo[idx * 2 + 0] = __halves2half2(lx, ly);
    lo[idx * 2 + 1] = __halves2half2(lz, lw);
}

// ---------------------------------------------------------------------------
// Kernel 2: split-fp16 HMMA GEMM (frozen R9 config: CTA 128x128, BK=32,
// 3-stage cp.async, 8 warps 2x4, warp 64x32, 2 CTAs/SM, hoisted ldsm)
// ---------------------------------------------------------------------------
#define BKC 32
#define NCHK (IN_K / BKC)   // 32

__device__ __forceinline__ void load_chunk(uint32_t sb, int st, int c, int bm, int bn, int tid) {
    const int k0 = c * BKC;
    const uint32_t base = sb + (uint32_t)st * STAGE_SZ;
#pragma unroll
    for (int i = 0; i < 2; i++) {
        int f = tid + i * 256;        // 0..511
        int row = f >> 2, ch = f & 3;
        uint32_t so = SWOFF(row, ch);
        size_t gA = (size_t)(bm + row) * IN_K + k0 + ch * 8;
        size_t gB = (size_t)(bn + row) * IN_K + k0 + ch * 8;
        cpasync16(base + T_AH + so, g_ah + gA);
        cpasync16(base + T_AL + so, g_al + gA);
        cpasync16(base + T_BH + so, g_bh + gB);
        cpasync16(base + T_BL + so, g_bl + gB);
    }
    asm volatile("cp.async.commit_group;" ::: "memory");
}

__global__ void __launch_bounds__(256, 2)
gemm_hmma(const float* __restrict__ bias) {
    extern __shared__ char smem[];
    const uint32_t sb = smem_to_u32(smem);
    const int tid = threadIdx.x, lane = tid & 31, warp = tid >> 5;
    const int bm = blockIdx.y * 128, bn = blockIdx.x * 128;
    const int wm = (warp >> 2) * 64, wn = (warp & 3) * 32;

    float acc[4][4][4];
#pragma unroll
    for (int a = 0; a < 4; a++)
#pragma unroll
        for (int b = 0; b < 4; b++)
#pragma unroll
            for (int d = 0; d < 4; d++) acc[a][b][d] = 0.0f;

    load_chunk(sb, 0, 0, bm, bn, tid);
    load_chunk(sb, 1, 1, bm, bn, tid);

    const int lrow = lane & 15, lcol = lane >> 4;

    for (int c = 0; c < NCHK; c++) {
        if (c == NCHK - 1) {
            asm volatile("cp.async.wait_group 0;" ::: "memory");
        } else {
            asm volatile("cp.async.wait_group 1;" ::: "memory");
        }
        __syncthreads();
        if (c + 2 < NCHK)
            load_chunk(sb, (c + 2) % NSTAGE, c + 2, bm, bn, tid);

        const uint32_t base = sb + (uint32_t)(c % NSTAGE) * STAGE_SZ;
#pragma unroll
        for (int ks = 0; ks < 2; ks++) {
            const int kc = ks * 2 + lcol;
            uint32_t a_h[4][4], a_l[4][4], b_h[4][2], b_l[4][2];

#pragma unroll
            for (int mf = 0; mf < 4; mf++)
                ldsm4(a_h[mf], base + T_AH + SWOFF(wm + mf * 16 + lrow, kc));
#pragma unroll
            for (int bg = 0; bg < 2; bg++) {
                uint32_t q[4];
                ldsm4(q, base + T_BH + SWOFF(wn + bg * 16 + lrow, kc));
                b_h[bg * 2 + 0][0] = q[0]; b_h[bg * 2 + 0][1] = q[2];
                b_h[bg * 2 + 1][0] = q[1]; b_h[bg * 2 + 1][1] = q[3];
            }
#pragma unroll
            for (int bg = 0; bg < 2; bg++) {
                uint32_t q[4];
                ldsm4(q, base + T_BL + SWOFF(wn + bg * 16 + lrow, kc));
                b_l[bg * 2 + 0][0] = q[0]; b_l[bg * 2 + 0][1] = q[2];
                b_l[bg * 2 + 1][0] = q[1]; b_l[bg * 2 + 1][1] = q[3];
            }
#pragma unroll
            for (int mf = 0; mf < 4; mf++)
                ldsm4(a_l[mf], base + T_AL + SWOFF(wm + mf * 16 + lrow, kc));

#pragma unroll
            for (int mf = 0; mf < 4; mf++)
#pragma unroll
                for (int nf = 0; nf < 4; nf++)
                    mma16816(acc[mf][nf], a_h[mf], b_h[nf]);
#pragma unroll
            for (int mf = 0; mf < 4; mf++)
#pragma unroll
                for (int nf = 0; nf < 4; nf++)
                    mma16816(acc[mf][nf], a_h[mf], b_l[nf]);
#pragma unroll
            for (int mf = 0; mf < 4; mf++)
#pragma unroll
                for (int nf = 0; nf < 4; nf++)
                    mma16816(acc[mf][nf], a_l[mf], b_h[nf]);
        }
    }

    const int mrow = lane >> 2, ncol = (lane & 3) * 2;
#pragma unroll
    for (int nf = 0; nf < 4; nf++) {
        const int n = bn + wn + nf * 8 + ncol;
        const float2 bv = *(const float2*)&bias[n];
#pragma unroll
        for (int mf = 0; mf < 4; mf++) {
            const int m0 = bm + wm + mf * 16 + mrow;
            float2 v0 = make_float2(acc[mf][nf][0] + bv.x, acc[mf][nf][1] + bv.y);
            float2 v1 = make_float2(acc[mf][nf][2] + bv.x, acc[mf][nf][3] + bv.y);
            *(float2*)&g_y[(size_t)m0 * OUT_N + n] = v0;
            *(float2*)&g_y[(size_t)(m0 + 8) * OUT_N + n] = v1;
        }
    }
}

// ---------------------------------------------------------------------------
// Kernel 3: row statistics + NF4 quantization, REGISTER-RESIDENT row:
// each thread keeps its 16 elements in registers (no smem row cache).
// Same element order per thread as R9 -> bit-identical statistics/output.
// ---------------------------------------------------------------------------
#define NTH 256
#define ELEM4 (OUT_N / 4 / NTH)   // 4 float4 per thread

__device__ __forceinline__ void ins4(float s[4], float v) {
    if (v < s[3]) {
        if (v < s[2]) {
            s[3] = s[2];
            if (v < s[1]) {
                s[2] = s[1];
                if (v < s[0]) { s[1] = s[0]; s[0] = v; }
                else          { s[1] = v; }
            } else s[2] = v;
        } else s[3] = v;
    }
}

__device__ __forceinline__ void merge4(float s[4], float b0, float b1, float b2, float b3) {
    float l0 = fminf(s[0], b3), l1 = fminf(s[1], b2);
    float l2 = fminf(s[2], b1), l3 = fminf(s[3], b0);
    float t0 = fminf(l0, l2), t2 = fmaxf(l0, l2);
    float t1 = fminf(l1, l3), t3 = fmaxf(l1, l3);
    s[0] = fminf(t0, t1); s[1] = fmaxf(t0, t1);
    s[2] = fminf(t2, t3); s[3] = fmaxf(t2, t3);
}

__device__ __forceinline__ void warp_merge4(float s[4]) {
#pragma unroll
    for (int off = 16; off >= 1; off >>= 1) {
        float b0 = __shfl_xor_sync(0xffffffffu, s[0], off);
        float b1 = __shfl_xor_sync(0xffffffffu, s[1], off);
        float b2 = __shfl_xor_sync(0xffffffffu, s[2], off);
        float b3 = __shfl_xor_sync(0xffffffffu, s[3], off);
        merge4(s, b0, b1, b2, b3);
    }
}

__global__ void __launch_bounds__(NTH)
row_quant(float* __restrict__ O) {
    __shared__ float stage[64];
    __shared__ float pool_min[8][4], pool_max[8][4];
    __shared__ int cnt_min, cnt_max;
    __shared__ float s_t4min, s_t4max;
    __shared__ float2 s_tab[32];
    __shared__ float s_lutv[16];
    __shared__ float s_lo, s_up, s_off, s_rng, s_inv;

    const int r    = blockIdx.x;
    const int tid  = threadIdx.x;
    const int lane = tid & 31;
    const int warp = tid >> 5;

    // Build bucket table + LUT (constants only; once per block)
    if (tid < 32) {
        float cl = tid * 0.0625f - 1.0f;
        float cr = cl + 0.0625f;
        int base = 0; float thr = INFINITY;
#pragma unroll
        for (int i = 0; i < 15; i++) {
            float m = c_mid[i];
            if (m < cl) base++;
            else if (m < cr) thr = m;
        }
        s_tab[tid] = make_float2(thr, (float)base);
    }
    if (tid < 16) s_lutv[tid] = __half2float(__float2half_rn(c_lut[tid]));
    if (tid == 0) { cnt_min = 0; cnt_max = 0; }

    const float4* yv = reinterpret_cast<const float4*>(g_y + (size_t)r * OUT_N);

    // Pass 1: load this thread's 16 elements into registers, min/max
    float4 vbuf[ELEM4];
    float mn = INFINITY, mx = -INFINITY;
#pragma unroll
    for (int i = 0; i < ELEM4; i++) {
        float4 v = yv[tid + i * NTH];
        vbuf[i] = v;
        mn = fminf(mn, fminf(fminf(v.x, v.y), fminf(v.z, v.w)));
        mx = fmaxf(mx, fmaxf(fmaxf(v.x, v.y), fmaxf(v.z, v.w)));
    }

    // Reduce 4 smallest thread-minima / thread-negated-maxima
    {
        float s[4] = { mn, INFINITY, INFINITY, INFINITY };
        float g[4] = { -mx, INFINITY, INFINITY, INFINITY };
        warp_merge4(s);
        warp_merge4(g);
        if (lane == 0) {
#pragma unroll
            for (int j = 0; j < 4; j++) { stage[warp * 4 + j] = s[j]; stage[32 + warp * 4 + j] = g[j]; }
        }
    }
    __syncthreads();
    if (warp == 0) {
        float ss[4], gg[4];
        if (lane < 8) {
#pragma unroll
            for (int j = 0; j < 4; j++) { ss[j] = stage[lane * 4 + j]; gg[j] = stage[32 + lane * 4 + j]; }
        } else {
#pragma unroll
            for (int j = 0; j < 4; j++) { ss[j] = INFINITY; gg[j] = INFINITY; }
        }
        warp_merge4(ss);
        warp_merge4(gg);
        if (lane == 0) { s_t4min = ss[3]; s_t4max = gg[3]; }
    }
    __syncthreads();

    // Detect & repair: qualifying threads rescan their registers exactly
    if (mn <= s_t4min) {
        int rank = atomicAdd(&cnt_min, 1);
        if (rank < 8) {
            float loc[4] = { INFINITY, INFINITY, INFINITY, INFINITY };
#pragma unroll
            for (int i = 0; i < ELEM4; i++) {
                float4 v = vbuf[i];
                ins4(loc, v.x); ins4(loc, v.y); ins4(loc, v.z); ins4(loc, v.w);
            }
#pragma unroll
            for (int j = 0; j < 4; j++) pool_min[rank][j] = loc[j];
        }
    }
    if (-mx <= s_t4max) {
        int rank = atomicAdd(&cnt_max, 1);
        if (rank < 8) {
            float loc[4] = { INFINITY, INFINITY, INFINITY, INFINITY };
#pragma unroll
            for (int i = 0; i < ELEM4; i++) {
                float4 v = vbuf[i];
                ins4(loc, -v.x); ins4(loc, -v.y); ins4(loc, -v.z); ins4(loc, -v.w);
            }
#pragma unroll
            for (int j = 0; j < 4; j++) pool_max[rank][j] = loc[j];
        }
    }
    __syncthreads();

    if (tid == 0) {
        float b[4] = { INFINITY, INFINITY, INFINITY, INFINITY };
        float t[4] = { INFINITY, INFINITY, INFINITY, INFINITY };
        int nm = cnt_min < 8 ? cnt_min : 8;
        int nM = cnt_max < 8 ? cnt_max : 8;
        for (int p = 0; p < nm; p++)
            for (int j = 0; j < 4; j++) ins4(b, pool_min[p][j]);
        for (int p = 0; p < nM; p++)
            for (int j = 0; j < 4; j++) ins4(t, pool_max[p][j]);
        // quantile positions: 0.0005*4095 = 2.0475 and 0.9995*4095 = 4092.9525
        float lo = b[2] + 0.0475f * (b[3] - b[2]);
        float h_lo = -t[3];                    // sorted[4092]
        float h_hi = -t[2];                    // sorted[4093]
        float up = h_lo + 0.9525f * (h_hi - h_lo);
        s_lo = lo; s_up = up;
        // Inlier extrema: min inlier = sorted[3], max inlier = sorted[4092]
        float m = b[3], M = h_lo;
        s_off = (M + m) * 0.5f;
        s_rng = (M - m) * 0.5f;
        s_inv = 1.0f / s_rng;
    }
    __syncthreads();
    const float lo = s_lo, up = s_up;
    const float offv = s_off, rng = s_rng, inv = s_inv;

    // Pass 2: quantize from registers via bucket table and write
    float4* ov = reinterpret_cast<float4*>(O + (size_t)r * OUT_N);
#pragma unroll
    for (int i = 0; i < ELEM4; i++) {
        float4 v = vbuf[i];
        float o[4];
        float in[4] = { v.x, v.y, v.z, v.w };
#pragma unroll
        for (int j = 0; j < 4; j++) {
            float y  = in[j];
            float yc = y - offv;
            float base;
            if (y <= lo || y >= up) {
                base = yc;
            } else {
                float sc = yc * inv;
                int cell = (int)fmaf(sc, 16.0f, 16.0f);
                cell = cell < 0 ? 0 : (cell > 31 ? 31 : cell);
                float2 t = s_tab[cell];
                int q = (int)t.y + (sc > t.x ? 1 : 0);
                base = s_lutv[q] * rng;
            }
            float outv = base + offv;
            if (!isfinite(outv)) outv = 0.0f;
            o[j] = outv;
        }
        ov[tid + i * NTH] = make_float4(o[0], o[1], o[2], o[3]);
    }
}

// ---------------------------------------------------------------------------
// Launch
// ---------------------------------------------------------------------------
extern "C" void kernel_launch(void* const* d_in, const int* in_sizes, int n_in,
                              void* d_out, int out_size) {
    (void)in_sizes; (void)n_in; (void)out_size;
    const float* x    = (const float*)d_in[0];   // [4096, 1024]
    const float* W    = (const float*)d_in[1];   // [4096, 1024]
    const float* bias = (const float*)d_in[2];   // [4096]
    float* out = (float*)d_out;                  // [4096, 4096]

    cudaFuncSetAttribute(gemm_hmma, cudaFuncAttributeMaxDynamicSharedMemorySize, GEMM_SMEM);

    split_fp16<<<(2 * A_F4) / 256, 256>>>(x, W);
    dim3 grid(OUT_N / 128, S_ROWS / 128);        // (32, 32)
    gemm_hmma<<<grid, 256, GEMM_SMEM>>>(bias);
    row_quant<<<S_ROWS, NTH>>>(out);
}

// round 13
// speedup vs baseline: 1.5822x; 1.0129x over previous
#include <cuda_runtime.h>
#include <cuda_fp16.h>
#include <math.h>
#include <stdint.h>

// Problem dimensions (fixed by the reference setup_inputs)
#define S_ROWS 4096
#define IN_K   1024
#define OUT_N  4096

// ---------------------------------------------------------------------------
// Device global scratch (no cudaMalloc allowed)
// ---------------------------------------------------------------------------
__device__ float g_y[(size_t)S_ROWS * OUT_N];                      // 64 MB
__device__ __align__(256) __half g_ah[(size_t)S_ROWS * IN_K];      // hi(x)
__device__ __align__(256) __half g_al[(size_t)S_ROWS * IN_K];      // x - hi(x)
__device__ __align__(256) __half g_bh[(size_t)OUT_N * IN_K];       // hi(W)
__device__ __align__(256) __half g_bl[(size_t)OUT_N * IN_K];       // W - hi(W)

// ---------------------------------------------------------------------------
// Helpers
// ---------------------------------------------------------------------------
__device__ __forceinline__ uint32_t smem_to_u32(const void* p) {
    uint32_t a;
    asm("{ .reg .u64 t; cvta.to.shared.u64 t, %1; cvt.u32.u64 %0, t; }" : "=r"(a) : "l"(p));
    return a;
}
__device__ __forceinline__ void cpasync16(uint32_t saddr, const void* g) {
    asm volatile("cp.async.cg.shared.global [%0], [%1], 16;" :: "r"(saddr), "l"(g));
}
__device__ __forceinline__ void ldsm4(uint32_t* r, uint32_t addr) {
    asm volatile("ldmatrix.sync.aligned.m8n8.x4.shared.b16 {%0,%1,%2,%3}, [%4];"
        : "=r"(r[0]), "=r"(r[1]), "=r"(r[2]), "=r"(r[3]) : "r"(addr));
}
__device__ __forceinline__ void mma16816(float* d, const uint32_t* a, const uint32_t* b) {
    asm volatile("mma.sync.aligned.m16n8k16.row.col.f32.f16.f16.f32 "
        "{%0,%1,%2,%3}, {%4,%5,%6,%7}, {%8,%9}, {%0,%1,%2,%3};"
        : "+f"(d[0]), "+f"(d[1]), "+f"(d[2]), "+f"(d[3])
        : "r"(a[0]), "r"(a[1]), "r"(a[2]), "r"(a[3]), "r"(b[0]), "r"(b[1]));
}

// smem per stage: AH(8K) AL(8K) BH(8K) BL(8K); 3 stages
#define SWOFF(row, c) ((uint32_t)((row) * 64 + (((c) ^ (((row) >> 1) & 3)) << 4)))
#define STAGE_SZ 32768
#define NSTAGE 3
#define T_AH 0
#define T_AL 8192
#define T_BH 16384
#define T_BL 24576
#define GEMM_SMEM (NSTAGE * STAGE_SZ)

// ---------------------------------------------------------------------------
// NF4 LUT + decision midpoints
// ---------------------------------------------------------------------------
#define LUTVALS -1.0f, -0.6961928009986877f, -0.5250730514526367f, \
    -0.39491748809814453f, -0.28444138169288635f, -0.18477343022823334f, \
    -0.09105003625154495f, 0.0f, 0.07958029955625534f, 0.16093020141124725f, \
    0.24611230194568634f, 0.33791524171829224f, 0.44070982933044434f, \
    0.5626170039176941f, 0.8726174235343933f, 1.0f

__constant__ float c_lut[16] = { LUTVALS };
__constant__ float c_mid[15] = {
    -0.8480964004993439f,  -0.6106329262256622f,  -0.4599952697753906f,
    -0.33967943489551544f, -0.23460740596055984f, -0.13791173323988914f,
    -0.045525018125772476f, 0.03979014977812767f,  0.1202552504837513f,
     0.2035212516784668f,   0.2920137718319893f,   0.3893125355243683f,
     0.5016634166240692f,   0.7176172137260437f,   0.9363087117671967f };

// ---------------------------------------------------------------------------
// Kernel 1: split fp32 -> (hi fp16, residual fp16). 2 independent float4
// per thread (MLP=2); same output bits as before.
// ---------------------------------------------------------------------------
#define A_F4 ((S_ROWS * IN_K) / 4)     // 1048576 float4 per matrix

__device__ __forceinline__ void split_one(float4 v, __half2* hi, __half2* lo, unsigned idx) {
    __half hx = __float2half_rn(v.x), hy = __float2half_rn(v.y);
    __half hz = __float2half_rn(v.z), hw = __float2half_rn(v.w);
    __half lx = __float2half_rn(v.x - __half2float(hx));
    __half ly = __float2half_rn(v.y - __half2float(hy));
    __half lz = __float2half_rn(v.z - __half2float(hz));
    __half lw = __float2half_rn(v.w - __half2float(hw));
    hi[idx * 2 + 0] = __halves2half2(hx, hy);
    hi[idx * 2 + 1] = __halves2half2(hz, hw);
    lo[idx * 2 + 0] = __halves2half2(lx, ly);
    lo[idx * 2 + 1] = __halves2half2(lz, lw);
}

__global__ void __launch_bounds__(256)
split_fp16(const float* __restrict__ A, const float* __restrict__ B) {
    // blocks [0, A_F4/512): A matrix; blocks [A_F4/512, 2*A_F4/512): B matrix
    unsigned b = blockIdx.x;
    const float4* src;
    __half2 *hi, *lo;
    unsigned base;
    if (b < A_F4 / 512) {
        src = (const float4*)A; hi = (__half2*)g_ah; lo = (__half2*)g_al;
        base = b * 512u + threadIdx.x;
    } else {
        src = (const float4*)B; hi = (__half2*)g_bh; lo = (__half2*)g_bl;
        base = (b - A_F4 / 512) * 512u + threadIdx.x;
    }
    // two independent loads in flight
    float4 v0 = src[base];
    float4 v1 = src[base + 256];
    split_one(v0, hi, lo, base);
    split_one(v1, hi, lo, base + 256);
}

// ---------------------------------------------------------------------------
// Kernel 2: split-fp16 HMMA GEMM (frozen R9 config: CTA 128x128, BK=32,
// 3-stage cp.async, 8 warps 2x4, warp 64x32, 2 CTAs/SM, hoisted ldsm)
// ---------------------------------------------------------------------------
#define BKC 32
#define NCHK (IN_K / BKC)   // 32

__device__ __forceinline__ void load_chunk(uint32_t sb, int st, int c, int bm, int bn, int tid) {
    const int k0 = c * BKC;
    const uint32_t base = sb + (uint32_t)st * STAGE_SZ;
#pragma unroll
    for (int i = 0; i < 2; i++) {
        int f = tid + i * 256;        // 0..511
        int row = f >> 2, ch = f & 3;
        uint32_t so = SWOFF(row, ch);
        size_t gA = (size_t)(bm + row) * IN_K + k0 + ch * 8;
        size_t gB = (size_t)(bn + row) * IN_K + k0 + ch * 8;
        cpasync16(base + T_AH + so, g_ah + gA);
        cpasync16(base + T_AL + so, g_al + gA);
        cpasync16(base + T_BH + so, g_bh + gB);
        cpasync16(base + T_BL + so, g_bl + gB);
    }
    asm volatile("cp.async.commit_group;" ::: "memory");
}

__global__ void __launch_bounds__(256, 2)
gemm_hmma(const float* __restrict__ bias) {
    extern __shared__ char smem[];
    const uint32_t sb = smem_to_u32(smem);
    const int tid = threadIdx.x, lane = tid & 31, warp = tid >> 5;
    const int bm = blockIdx.y * 128, bn = blockIdx.x * 128;
    const int wm = (warp >> 2) * 64, wn = (warp & 3) * 32;

    float acc[4][4][4];
#pragma unroll
    for (int a = 0; a < 4; a++)
#pragma unroll
        for (int b = 0; b < 4; b++)
#pragma unroll
            for (int d = 0; d < 4; d++) acc[a][b][d] = 0.0f;

    load_chunk(sb, 0, 0, bm, bn, tid);
    load_chunk(sb, 1, 1, bm, bn, tid);

    const int lrow = lane & 15, lcol = lane >> 4;

    for (int c = 0; c < NCHK; c++) {
        if (c == NCHK - 1) {
            asm volatile("cp.async.wait_group 0;" ::: "memory");
        } else {
            asm volatile("cp.async.wait_group 1;" ::: "memory");
        }
        __syncthreads();
        if (c + 2 < NCHK)
            load_chunk(sb, (c + 2) % NSTAGE, c + 2, bm, bn, tid);

        const uint32_t base = sb + (uint32_t)(c % NSTAGE) * STAGE_SZ;
#pragma unroll
        for (int ks = 0; ks < 2; ks++) {
            const int kc = ks * 2 + lcol;
            uint32_t a_h[4][4], a_l[4][4], b_h[4][2], b_l[4][2];

#pragma unroll
            for (int mf = 0; mf < 4; mf++)
                ldsm4(a_h[mf], base + T_AH + SWOFF(wm + mf * 16 + lrow, kc));
#pragma unroll
            for (int bg = 0; bg < 2; bg++) {
                uint32_t q[4];
                ldsm4(q, base + T_BH + SWOFF(wn + bg * 16 + lrow, kc));
                b_h[bg * 2 + 0][0] = q[0]; b_h[bg * 2 + 0][1] = q[2];
                b_h[bg * 2 + 1][0] = q[1]; b_h[bg * 2 + 1][1] = q[3];
            }
#pragma unroll
            for (int bg = 0; bg < 2; bg++) {
                uint32_t q[4];
                ldsm4(q, base + T_BL + SWOFF(wn + bg * 16 + lrow, kc));
                b_l[bg * 2 + 0][0] = q[0]; b_l[bg * 2 + 0][1] = q[2];
                b_l[bg * 2 + 1][0] = q[1]; b_l[bg * 2 + 1][1] = q[3];
            }
#pragma unroll
            for (int mf = 0; mf < 4; mf++)
                ldsm4(a_l[mf], base + T_AL + SWOFF(wm + mf * 16 + lrow, kc));

#pragma unroll
            for (int mf = 0; mf < 4; mf++)
#pragma unroll
                for (int nf = 0; nf < 4; nf++)
                    mma16816(acc[mf][nf], a_h[mf], b_h[nf]);
#pragma unroll
            for (int mf = 0; mf < 4; mf++)
#pragma unroll
                for (int nf = 0; nf < 4; nf++)
                    mma16816(acc[mf][nf], a_h[mf], b_l[nf]);
#pragma unroll
            for (int mf = 0; mf < 4; mf++)
#pragma unroll
                for (int nf = 0; nf < 4; nf++)
                    mma16816(acc[mf][nf], a_l[mf], b_h[nf]);
        }
    }

    const int mrow = lane >> 2, ncol = (lane & 3) * 2;
#pragma unroll
    for (int nf = 0; nf < 4; nf++) {
        const int n = bn + wn + nf * 8 + ncol;
        const float2 bv = *(const float2*)&bias[n];
#pragma unroll
        for (int mf = 0; mf < 4; mf++) {
            const int m0 = bm + wm + mf * 16 + mrow;
            float2 v0 = make_float2(acc[mf][nf][0] + bv.x, acc[mf][nf][1] + bv.y);
            float2 v1 = make_float2(acc[mf][nf][2] + bv.x, acc[mf][nf][3] + bv.y);
            *(float2*)&g_y[(size_t)m0 * OUT_N + n] = v0;
            *(float2*)&g_y[(size_t)(m0 + 8) * OUT_N + n] = v1;
        }
    }
}

// ---------------------------------------------------------------------------
// Kernel 3: row statistics + NF4 quantization (exact R9 version: smem row
// cache, cheap min/max pass + exact detect-and-repair, order-statistic
// extrema, bucketized NF4 lookup).
// ---------------------------------------------------------------------------
#define NTH 256

__device__ __forceinline__ void ins4(float s[4], float v) {
    if (v < s[3]) {
        if (v < s[2]) {
            s[3] = s[2];
            if (v < s[1]) {
                s[2] = s[1];
                if (v < s[0]) { s[1] = s[0]; s[0] = v; }
                else          { s[1] = v; }
            } else s[2] = v;
        } else s[3] = v;
    }
}

__device__ __forceinline__ void merge4(float s[4], float b0, float b1, float b2, float b3) {
    float l0 = fminf(s[0], b3), l1 = fminf(s[1], b2);
    float l2 = fminf(s[2], b1), l3 = fminf(s[3], b0);
    float t0 = fminf(l0, l2), t2 = fmaxf(l0, l2);
    float t1 = fminf(l1, l3), t3 = fmaxf(l1, l3);
    s[0] = fminf(t0, t1); s[1] = fmaxf(t0, t1);
    s[2] = fminf(t2, t3); s[3] = fmaxf(t2, t3);
}

__device__ __forceinline__ void warp_merge4(float s[4]) {
#pragma unroll
    for (int off = 16; off >= 1; off >>= 1) {
        float b0 = __shfl_xor_sync(0xffffffffu, s[0], off);
        float b1 = __shfl_xor_sync(0xffffffffu, s[1], off);
        float b2 = __shfl_xor_sync(0xffffffffu, s[2], off);
        float b3 = __shfl_xor_sync(0xffffffffu, s[3], off);
        merge4(s, b0, b1, b2, b3);
    }
}

__global__ void __launch_bounds__(NTH)
row_quant(float* __restrict__ O) {
    __shared__ float row[OUT_N];
    __shared__ float stage[64];
    __shared__ float pool_min[8][4], pool_max[8][4];
    __shared__ int cnt_min, cnt_max;
    __shared__ float s_t4min, s_t4max;
    __shared__ float2 s_tab[32];
    __shared__ float s_lutv[16];
    __shared__ float s_lo, s_up, s_off, s_rng, s_inv;

    const int r    = blockIdx.x;
    const int tid  = threadIdx.x;
    const int lane = tid & 31;
    const int warp = tid >> 5;

    if (tid < 32) {
        float cl = tid * 0.0625f - 1.0f;
        float cr = cl + 0.0625f;
        int base = 0; float thr = INFINITY;
#pragma unroll
        for (int i = 0; i < 15; i++) {
            float m = c_mid[i];
            if (m < cl) base++;
            else if (m < cr) thr = m;
        }
        s_tab[tid] = make_float2(thr, (float)base);
    }
    if (tid < 16) s_lutv[tid] = __half2float(__float2half_rn(c_lut[tid]));
    if (tid == 0) { cnt_min = 0; cnt_max = 0; }

    const float4* yv = reinterpret_cast<const float4*>(g_y + (size_t)r * OUT_N);
    float4* rv = reinterpret_cast<float4*>(row);

    float mn = INFINITY, mx = -INFINITY;
#pragma unroll
    for (int i = 0; i < OUT_N / 4 / NTH; i++) {
        int idx = tid + i * NTH;
        float4 v = yv[idx];
        rv[idx] = v;
        mn = fminf(mn, fminf(fminf(v.x, v.y), fminf(v.z, v.w)));
        mx = fmaxf(mx, fmaxf(fmaxf(v.x, v.y), fmaxf(v.z, v.w)));
    }

    {
        float s[4] = { mn, INFINITY, INFINITY, INFINITY };
        float g[4] = { -mx, INFINITY, INFINITY, INFINITY };
        warp_merge4(s);
        warp_merge4(g);
        if (lane == 0) {
#pragma unroll
            for (int j = 0; j < 4; j++) { stage[warp * 4 + j] = s[j]; stage[32 + warp * 4 + j] = g[j]; }
        }
    }
    __syncthreads();
    if (warp == 0) {
        float ss[4], gg[4];
        if (lane < 8) {
#pragma unroll
            for (int j = 0; j < 4; j++) { ss[j] = stage[lane * 4 + j]; gg[j] = stage[32 + lane * 4 + j]; }
        } else {
#pragma unroll
            for (int j = 0; j < 4; j++) { ss[j] = INFINITY; gg[j] = INFINITY; }
        }
        warp_merge4(ss);
        warp_merge4(gg);
        if (lane == 0) { s_t4min = ss[3]; s_t4max = gg[3]; }
    }
    __syncthreads();

    if (mn <= s_t4min) {
        int rank = atomicAdd(&cnt_min, 1);
        if (rank < 8) {
            float loc[4] = { INFINITY, INFINITY, INFINITY, INFINITY };
#pragma unroll
            for (int i = 0; i < OUT_N / 4 / NTH; i++) {
                float4 v = rv[tid + i * NTH];
                ins4(loc, v.x); ins4(loc, v.y); ins4(loc, v.z); ins4(loc, v.w);
            }
#pragma unroll
            for (int j = 0; j < 4; j++) pool_min[rank][j] = loc[j];
        }
    }
    if (-mx <= s_t4max) {
        int rank = atomicAdd(&cnt_max, 1);
        if (rank < 8) {
            float loc[4] = { INFINITY, INFINITY, INFINITY, INFINITY };
#pragma unroll
            for (int i = 0; i < OUT_N / 4 / NTH; i++) {
                float4 v = rv[tid + i * NTH];
                ins4(loc, -v.x); ins4(loc, -v.y); ins4(loc, -v.z); ins4(loc, -v.w);
            }
#pragma unroll
            for (int j = 0; j < 4; j++) pool_max[rank][j] = loc[j];
        }
    }
    __syncthreads();

    if (tid == 0) {
        float b[4] = { INFINITY, INFINITY, INFINITY, INFINITY };
        float t[4] = { INFINITY, INFINITY, INFINITY, INFINITY };
        int nm = cnt_min < 8 ? cnt_min : 8;
        int nM = cnt_max < 8 ? cnt_max : 8;
        for (int p = 0; p < nm; p++)
            for (int j = 0; j < 4; j++) ins4(b, pool_min[p][j]);
        for (int p = 0; p < nM; p++)
            for (int j = 0; j < 4; j++) ins4(t, pool_max[p][j]);
        // quantile positions: 0.0005*4095 = 2.0475 and 0.9995*4095 = 4092.9525
        float lo = b[2] + 0.0475f * (b[3] - b[2]);
        float h_lo = -t[3];                    // sorted[4092]
        float h_hi = -t[2];                    // sorted[4093]
        float up = h_lo + 0.9525f * (h_hi - h_lo);
        s_lo = lo; s_up = up;
        // Inlier extrema: min inlier = sorted[3], max inlier = sorted[4092]
        float m = b[3], M = h_lo;
        s_off = (M + m) * 0.5f;
        s_rng = (M - m) * 0.5f;
        s_inv = 1.0f / s_rng;
    }
    __syncthreads();
    const float lo = s_lo, up = s_up;
    const float offv = s_off, rng = s_rng, inv = s_inv;

    float4* ov = reinterpret_cast<float4*>(O + (size_t)r * OUT_N);
#pragma unroll
    for (int i = 0; i < OUT_N / 4 / NTH; i++) {
        int idx = tid + i * NTH;
        float4 v = rv[idx];
        float o[4];
        float in[4] = { v.x, v.y, v.z, v.w };
#pragma unroll
        for (int j = 0; j < 4; j++) {
            float y  = in[j];
            float yc = y - offv;
            float base;
            if (y <= lo || y >= up) {
                base = yc;
            } else {
                float sc = yc * inv;
                int cell = (int)fmaf(sc, 16.0f, 16.0f);
                cell = cell < 0 ? 0 : (cell > 31 ? 31 : cell);
                float2 t = s_tab[cell];
                int q = (int)t.y + (sc > t.x ? 1 : 0);
                base = s_lutv[q] * rng;
            }
            float outv = base + offv;
            if (!isfinite(outv)) outv = 0.0f;
            o[j] = outv;
        }
        ov[idx] = make_float4(o[0], o[1], o[2], o[3]);
    }
}

// ---------------------------------------------------------------------------
// Launch
// ---------------------------------------------------------------------------
extern "C" void kernel_launch(void* const* d_in, const int* in_sizes, int n_in,
                              void* d_out, int out_size) {
    (void)in_sizes; (void)n_in; (void)out_size;
    const float* x    = (const float*)d_in[0];   // [4096, 1024]
    const float* W    = (const float*)d_in[1];   // [4096, 1024]
    const float* bias = (const float*)d_in[2];   // [4096]
    float* out = (float*)d_out;                  // [4096, 4096]

    cudaFuncSetAttribute(gemm_hmma, cudaFuncAttributeMaxDynamicSharedMemorySize, GEMM_SMEM);

    split_fp16<<<(2 * A_F4) / 512, 256>>>(x, W);
    dim3 grid(OUT_N / 128, S_ROWS / 128);        // (32, 32)
    gemm_hmma<<<grid, 256, GEMM_SMEM>>>(bias);
    row_quant<<<S_ROWS, NTH>>>(out);
}

// round 14
// speedup vs baseline: 1.5946x; 1.0078x over previous
#include <cuda_runtime.h>
#include <cuda_fp16.h>
#include <math.h>
#include <stdint.h>

// Problem dimensions (fixed by the reference setup_inputs)
#define S_ROWS 4096
#define IN_K   1024
#define OUT_N  4096

// ---------------------------------------------------------------------------
// Device global scratch (no cudaMalloc allowed)
// ---------------------------------------------------------------------------
__device__ float g_y[(size_t)S_ROWS * OUT_N];                      // 64 MB
__device__ __align__(256) __half g_ah[(size_t)S_ROWS * IN_K];      // hi(x)
__device__ __align__(256) __half g_al[(size_t)S_ROWS * IN_K];      // x - hi(x)
__device__ __align__(256) __half g_bh[(size_t)OUT_N * IN_K];       // hi(W)
__device__ __align__(256) __half g_bl[(size_t)OUT_N * IN_K];       // W - hi(W)

// ---------------------------------------------------------------------------
// Helpers
// ---------------------------------------------------------------------------
__device__ __forceinline__ uint32_t smem_to_u32(const void* p) {
    uint32_t a;
    asm("{ .reg .u64 t; cvta.to.shared.u64 t, %1; cvt.u32.u64 %0, t; }" : "=r"(a) : "l"(p));
    return a;
}
__device__ __forceinline__ void cpasync16(uint32_t saddr, const void* g) {
    asm volatile("cp.async.cg.shared.global [%0], [%1], 16;" :: "r"(saddr), "l"(g));
}
__device__ __forceinline__ void ldsm4(uint32_t* r, uint32_t addr) {
    asm volatile("ldmatrix.sync.aligned.m8n8.x4.shared.b16 {%0,%1,%2,%3}, [%4];"
        : "=r"(r[0]), "=r"(r[1]), "=r"(r[2]), "=r"(r[3]) : "r"(addr));
}
__device__ __forceinline__ void mma16816(float* d, const uint32_t* a, const uint32_t* b) {
    asm volatile("mma.sync.aligned.m16n8k16.row.col.f32.f16.f16.f32 "
        "{%0,%1,%2,%3}, {%4,%5,%6,%7}, {%8,%9}, {%0,%1,%2,%3};"
        : "+f"(d[0]), "+f"(d[1]), "+f"(d[2]), "+f"(d[3])
        : "r"(a[0]), "r"(a[1]), "r"(a[2]), "r"(a[3]), "r"(b[0]), "r"(b[1]));
}

// smem per stage: AH(8K) AL(8K) BH(8K) BL(8K); 3 stages
#define SWOFF(row, c) ((uint32_t)((row) * 64 + (((c) ^ (((row) >> 1) & 3)) << 4)))
#define STAGE_SZ 32768
#define NSTAGE 3
#define T_AH 0
#define T_AL 8192
#define T_BH 16384
#define T_BL 24576
#define GEMM_SMEM (NSTAGE * STAGE_SZ)

// ---------------------------------------------------------------------------
// NF4 LUT + decision midpoints
// ---------------------------------------------------------------------------
#define LUTVALS -1.0f, -0.6961928009986877f, -0.5250730514526367f, \
    -0.39491748809814453f, -0.28444138169288635f, -0.18477343022823334f, \
    -0.09105003625154495f, 0.0f, 0.07958029955625534f, 0.16093020141124725f, \
    0.24611230194568634f, 0.33791524171829224f, 0.44070982933044434f, \
    0.5626170039176941f, 0.8726174235343933f, 1.0f

__constant__ float c_lut[16] = { LUTVALS };
__constant__ float c_mid[15] = {
    -0.8480964004993439f,  -0.6106329262256622f,  -0.4599952697753906f,
    -0.33967943489551544f, -0.23460740596055984f, -0.13791173323988914f,
    -0.045525018125772476f, 0.03979014977812767f,  0.1202552504837513f,
     0.2035212516784668f,   0.2920137718319893f,   0.3893125355243683f,
     0.5016634166240692f,   0.7176172137260437f,   0.9363087117671967f };

// ---------------------------------------------------------------------------
// Kernel 1: split fp32 -> (hi fp16, residual fp16). 4 independent float4
// per thread (MLP=4); output bits unchanged.
// ---------------------------------------------------------------------------
#define A_F4 ((S_ROWS * IN_K) / 4)     // 1048576 float4 per matrix

__device__ __forceinline__ void split_one(float4 v, __half2* hi, __half2* lo, unsigned idx) {
    __half hx = __float2half_rn(v.x), hy = __float2half_rn(v.y);
    __half hz = __float2half_rn(v.z), hw = __float2half_rn(v.w);
    __half lx = __float2half_rn(v.x - __half2float(hx));
    __half ly = __float2half_rn(v.y - __half2float(hy));
    __half lz = __float2half_rn(v.z - __half2float(hz));
    __half lw = __float2half_rn(v.w - __half2float(hw));
    hi[idx * 2 + 0] = __halves2half2(hx, hy);
    hi[idx * 2 + 1] = __halves2half2(hz, hw);
    lo[idx * 2 + 0] = __halves2half2(lx, ly);
    lo[idx * 2 + 1] = __halves2half2(lz, lw);
}

__global__ void __launch_bounds__(256)
split_fp16(const float* __restrict__ A, const float* __restrict__ B) {
    // blocks [0, A_F4/1024): A matrix; rest: B matrix. 4 float4 per thread.
    unsigned b = blockIdx.x;
    const float4* src;
    __half2 *hi, *lo;
    unsigned base;
    if (b < A_F4 / 1024) {
        src = (const float4*)A; hi = (__half2*)g_ah; lo = (__half2*)g_al;
        base = b * 1024u + threadIdx.x;
    } else {
        src = (const float4*)B; hi = (__half2*)g_bh; lo = (__half2*)g_bl;
        base = (b - A_F4 / 1024) * 1024u + threadIdx.x;
    }
    float4 v0 = src[base];
    float4 v1 = src[base + 256];
    float4 v2 = src[base + 512];
    float4 v3 = src[base + 768];
    split_one(v0, hi, lo, base);
    split_one(v1, hi, lo, base + 256);
    split_one(v2, hi, lo, base + 512);
    split_one(v3, hi, lo, base + 768);
}

// ---------------------------------------------------------------------------
// Kernel 2: split-fp16 HMMA GEMM. CTA 128x128, BK=32, 3-stage cp.async,
// 8 warps 2x4, warp 64x32, 2 CTAs/SM. Mainloop unrolled by NSTAGE so stage
// offsets are compile-time constants. Accumulation order identical to
// R4-R13 (rel_err-preserving).
// ---------------------------------------------------------------------------
#define BKC 32
#define NCHK (IN_K / BKC)   // 32

template<int ST>
__device__ __forceinline__ void load_chunk_s(uint32_t sb, int c, int bm, int bn, int tid) {
    const int k0 = c * BKC;
    const uint32_t base = sb + (uint32_t)(ST * STAGE_SZ);
#pragma unroll
    for (int i = 0; i < 2; i++) {
        int f = tid + i * 256;        // 0..511
        int row = f >> 2, ch = f & 3;
        uint32_t so = SWOFF(row, ch);
        size_t gA = (size_t)(bm + row) * IN_K + k0 + ch * 8;
        size_t gB = (size_t)(bn + row) * IN_K + k0 + ch * 8;
        cpasync16(base + T_AH + so, g_ah + gA);
        cpasync16(base + T_AL + so, g_al + gA);
        cpasync16(base + T_BH + so, g_bh + gB);
        cpasync16(base + T_BL + so, g_bl + gB);
    }
    asm volatile("cp.async.commit_group;" ::: "memory");
}

// One mainloop body for chunk c resident in compile-time stage ST.
// LOADST = stage receiving chunk c+2 (compile-time), LAST = (c == NCHK-1).
template<int ST, int LOADST, bool DOLOAD, bool LAST>
__device__ __forceinline__ void gemm_body(uint32_t sb, int c, int bm, int bn, int tid,
                                          int wm, int wn, int lrow, int lcol,
                                          float acc[4][4][4]) {
    if (LAST) {
        asm volatile("cp.async.wait_group 0;" ::: "memory");
    } else {
        asm volatile("cp.async.wait_group 1;" ::: "memory");
    }
    __syncthreads();
    if (DOLOAD)
        load_chunk_s<LOADST>(sb, c + 2, bm, bn, tid);

    const uint32_t base = sb + (uint32_t)(ST * STAGE_SZ);
#pragma unroll
    for (int ks = 0; ks < 2; ks++) {
        const int kc = ks * 2 + lcol;
        uint32_t a_h[4][4], a_l[4][4], b_h[4][2], b_l[4][2];

#pragma unroll
        for (int mf = 0; mf < 4; mf++)
            ldsm4(a_h[mf], base + T_AH + SWOFF(wm + mf * 16 + lrow, kc));
#pragma unroll
        for (int bg = 0; bg < 2; bg++) {
            uint32_t q[4];
            ldsm4(q, base + T_BH + SWOFF(wn + bg * 16 + lrow, kc));
            b_h[bg * 2 + 0][0] = q[0]; b_h[bg * 2 + 0][1] = q[2];
            b_h[bg * 2 + 1][0] = q[1]; b_h[bg * 2 + 1][1] = q[3];
        }
#pragma unroll
        for (int bg = 0; bg < 2; bg++) {
            uint32_t q[4];
            ldsm4(q, base + T_BL + SWOFF(wn + bg * 16 + lrow, kc));
            b_l[bg * 2 + 0][0] = q[0]; b_l[bg * 2 + 0][1] = q[2];
            b_l[bg * 2 + 1][0] = q[1]; b_l[bg * 2 + 1][1] = q[3];
        }
#pragma unroll
        for (int mf = 0; mf < 4; mf++)
            ldsm4(a_l[mf], base + T_AL + SWOFF(wm + mf * 16 + lrow, kc));

#pragma unroll
        for (int mf = 0; mf < 4; mf++)
#pragma unroll
            for (int nf = 0; nf < 4; nf++)
                mma16816(acc[mf][nf], a_h[mf], b_h[nf]);
#pragma unroll
        for (int mf = 0; mf < 4; mf++)
#pragma unroll
            for (int nf = 0; nf < 4; nf++)
                mma16816(acc[mf][nf], a_h[mf], b_l[nf]);
#pragma unroll
        for (int mf = 0; mf < 4; mf++)
#pragma unroll
            for (int nf = 0; nf < 4; nf++)
                mma16816(acc[mf][nf], a_l[mf], b_h[nf]);
    }
}

__global__ void __launch_bounds__(256, 2)
gemm_hmma(const float* __restrict__ bias) {
    extern __shared__ char smem[];
    const uint32_t sb = smem_to_u32(smem);
    const int tid = threadIdx.x, lane = tid & 31, warp = tid >> 5;
    const int bm = blockIdx.y * 128, bn = blockIdx.x * 128;
    const int wm = (warp >> 2) * 64, wn = (warp & 3) * 32;

    float acc[4][4][4];
#pragma unroll
    for (int a = 0; a < 4; a++)
#pragma unroll
        for (int b = 0; b < 4; b++)
#pragma unroll
            for (int d = 0; d < 4; d++) acc[a][b][d] = 0.0f;

    load_chunk_s<0>(sb, 0, bm, bn, tid);
    load_chunk_s<1>(sb, 1, bm, bn, tid);

    const int lrow = lane & 15, lcol = lane >> 4;

    // chunks 0..29 in groups of 3 (stages 0,1,2), then peeled 30 (stage 0),
    // 31 (stage 1). Loads target stage (c+2)%3, compile-time per position.
#pragma unroll 1
    for (int cc = 0; cc < 30; cc += 3) {
        gemm_body<0, 2, true,  false>(sb, cc + 0, bm, bn, tid, wm, wn, lrow, lcol, acc);
        gemm_body<1, 0, true,  false>(sb, cc + 1, bm, bn, tid, wm, wn, lrow, lcol, acc);
        gemm_body<2, 1, true,  false>(sb, cc + 2, bm, bn, tid, wm, wn, lrow, lcol, acc);
    }
    gemm_body<0, 2, false, false>(sb, 30, bm, bn, tid, wm, wn, lrow, lcol, acc);
    gemm_body<1, 0, false, true >(sb, 31, bm, bn, tid, wm, wn, lrow, lcol, acc);

    const int mrow = lane >> 2, ncol = (lane & 3) * 2;
#pragma unroll
    for (int nf = 0; nf < 4; nf++) {
        const int n = bn + wn + nf * 8 + ncol;
        const float2 bv = *(const float2*)&bias[n];
#pragma unroll
        for (int mf = 0; mf < 4; mf++) {
            const int m0 = bm + wm + mf * 16 + mrow;
            float2 v0 = make_float2(acc[mf][nf][0] + bv.x, acc[mf][nf][1] + bv.y);
            float2 v1 = make_float2(acc[mf][nf][2] + bv.x, acc[mf][nf][3] + bv.y);
            *(float2*)&g_y[(size_t)m0 * OUT_N + n] = v0;
            *(float2*)&g_y[(size_t)(m0 + 8) * OUT_N + n] = v1;
        }
    }
}

// ---------------------------------------------------------------------------
// Kernel 3: row statistics + NF4 quantization (frozen R9 version: smem row
// cache, cheap min/max pass + exact detect-and-repair, order-statistic
// extrema, bucketized NF4 lookup).
// ---------------------------------------------------------------------------
#define NTH 256

__device__ __forceinline__ void ins4(float s[4], float v) {
    if (v < s[3]) {
        if (v < s[2]) {
            s[3] = s[2];
            if (v < s[1]) {
                s[2] = s[1];
                if (v < s[0]) { s[1] = s[0]; s[0] = v; }
                else          { s[1] = v; }
            } else s[2] = v;
        } else s[3] = v;
    }
}

__device__ __forceinline__ void merge4(float s[4], float b0, float b1, float b2, float b3) {
    float l0 = fminf(s[0], b3), l1 = fminf(s[1], b2);
    float l2 = fminf(s[2], b1), l3 = fminf(s[3], b0);
    float t0 = fminf(l0, l2), t2 = fmaxf(l0, l2);
    float t1 = fminf(l1, l3), t3 = fmaxf(l1, l3);
    s[0] = fminf(t0, t1); s[1] = fmaxf(t0, t1);
    s[2] = fminf(t2, t3); s[3] = fmaxf(t2, t3);
}

__device__ __forceinline__ void warp_merge4(float s[4]) {
#pragma unroll
    for (int off = 16; off >= 1; off >>= 1) {
        float b0 = __shfl_xor_sync(0xffffffffu, s[0], off);
        float b1 = __shfl_xor_sync(0xffffffffu, s[1], off);
        float b2 = __shfl_xor_sync(0xffffffffu, s[2], off);
        float b3 = __shfl_xor_sync(0xffffffffu, s[3], off);
        merge4(s, b0, b1, b2, b3);
    }
}

__global__ void __launch_bounds__(NTH)
row_quant(float* __restrict__ O) {
    __shared__ float row[OUT_N];
    __shared__ float stage[64];
    __shared__ float pool_min[8][4], pool_max[8][4];
    __shared__ int cnt_min, cnt_max;
    __shared__ float s_t4min, s_t4max;
    __shared__ float2 s_tab[32];
    __shared__ float s_lutv[16];
    __shared__ float s_lo, s_up, s_off, s_rng, s_inv;

    const int r    = blockIdx.x;
    const int tid  = threadIdx.x;
    const int lane = tid & 31;
    const int warp = tid >> 5;

    if (tid < 32) {
        float cl = tid * 0.0625f - 1.0f;
        float cr = cl + 0.0625f;
        int base = 0; float thr = INFINITY;
#pragma unroll
        for (int i = 0; i < 15; i++) {
            float m = c_mid[i];
            if (m < cl) base++;
            else if (m < cr) thr = m;
        }
        s_tab[tid] = make_float2(thr, (float)base);
    }
    if (tid < 16) s_lutv[tid] = __half2float(__float2half_rn(c_lut[tid]));
    if (tid == 0) { cnt_min = 0; cnt_max = 0; }

    const float4* yv = reinterpret_cast<const float4*>(g_y + (size_t)r * OUT_N);
    float4* rv = reinterpret_cast<float4*>(row);

    float mn = INFINITY, mx = -INFINITY;
#pragma unroll
    for (int i = 0; i < OUT_N / 4 / NTH; i++) {
        int idx = tid + i * NTH;
        float4 v = yv[idx];
        rv[idx] = v;
        mn = fminf(mn, fminf(fminf(v.x, v.y), fminf(v.z, v.w)));
        mx = fmaxf(mx, fmaxf(fmaxf(v.x, v.y), fmaxf(v.z, v.w)));
    }

    {
        float s[4] = { mn, INFINITY, INFINITY, INFINITY };
        float g[4] = { -mx, INFINITY, INFINITY, INFINITY };
        warp_merge4(s);
        warp_merge4(g);
        if (lane == 0) {
#pragma unroll
            for (int j = 0; j < 4; j++) { stage[warp * 4 + j] = s[j]; stage[32 + warp * 4 + j] = g[j]; }
        }
    }
    __syncthreads();
    if (warp == 0) {
        float ss[4], gg[4];
        if (lane < 8) {
#pragma unroll
            for (int j = 0; j < 4; j++) { ss[j] = stage[lane * 4 + j]; gg[j] = stage[32 + lane * 4 + j]; }
        } else {
#pragma unroll
            for (int j = 0; j < 4; j++) { ss[j] = INFINITY; gg[j] = INFINITY; }
        }
        warp_merge4(ss);
        warp_merge4(gg);
        if (lane == 0) { s_t4min = ss[3]; s_t4max = gg[3]; }
    }
    __syncthreads();

    if (mn <= s_t4min) {
        int rank = atomicAdd(&cnt_min, 1);
        if (rank < 8) {
            float loc[4] = { INFINITY, INFINITY, INFINITY, INFINITY };
#pragma unroll
            for (int i = 0; i < OUT_N / 4 / NTH; i++) {
                float4 v = rv[tid + i * NTH];
                ins4(loc, v.x); ins4(loc, v.y); ins4(loc, v.z); ins4(loc, v.w);
            }
#pragma unroll
            for (int j = 0; j < 4; j++) pool_min[rank][j] = loc[j];
        }
    }
    if (-mx <= s_t4max) {
        int rank = atomicAdd(&cnt_max, 1);
        if (rank < 8) {
            float loc[4] = { INFINITY, INFINITY, INFINITY, INFINITY };
#pragma unroll
            for (int i = 0; i < OUT_N / 4 / NTH; i++) {
                float4 v = rv[tid + i * NTH];
                ins4(loc, -v.x); ins4(loc, -v.y); ins4(loc, -v.z); ins4(loc, -v.w);
            }
#pragma unroll
            for (int j = 0; j < 4; j++) pool_max[rank][j] = loc[j];
        }
    }
    __syncthreads();

    if (tid == 0) {
        float b[4] = { INFINITY, INFINITY, INFINITY, INFINITY };
        float t[4] = { INFINITY, INFINITY, INFINITY, INFINITY };
        int nm = cnt_min < 8 ? cnt_min : 8;
        int nM = cnt_max < 8 ? cnt_max : 8;
        for (int p = 0; p < nm; p++)
            for (int j = 0; j < 4; j++) ins4(b, pool_min[p][j]);
        for (int p = 0; p < nM; p++)
            for (int j = 0; j < 4; j++) ins4(t, pool_max[p][j]);
        // quantile positions: 0.0005*4095 = 2.0475 and 0.9995*4095 = 4092.9525
        float lo = b[2] + 0.0475f * (b[3] - b[2]);
        float h_lo = -t[3];                    // sorted[4092]
        float h_hi = -t[2];                    // sorted[4093]
        float up = h_lo + 0.9525f * (h_hi - h_lo);
        s_lo = lo; s_up = up;
        // Inlier extrema: min inlier = sorted[3], max inlier = sorted[4092]
        float m = b[3], M = h_lo;
        s_off = (M + m) * 0.5f;
        s_rng = (M - m) * 0.5f;
        s_inv = 1.0f / s_rng;
    }
    __syncthreads();
    const float lo = s_lo, up = s_up;
    const float offv = s_off, rng = s_rng, inv = s_inv;

    float4* ov = reinterpret_cast<float4*>(O + (size_t)r * OUT_N);
#pragma unroll
    for (int i = 0; i < OUT_N / 4 / NTH; i++) {
        int idx = tid + i * NTH;
        float4 v = rv[idx];
        float o[4];
        float in[4] = { v.x, v.y, v.z, v.w };
#pragma unroll
        for (int j = 0; j < 4; j++) {
            float y  = in[j];
            float yc = y - offv;
            float base;
            if (y <= lo || y >= up) {
                base = yc;
            } else {
                float sc = yc * inv;
                int cell = (int)fmaf(sc, 16.0f, 16.0f);
                cell = cell < 0 ? 0 : (cell > 31 ? 31 : cell);
                float2 t = s_tab[cell];
                int q = (int)t.y + (sc > t.x ? 1 : 0);
                base = s_lutv[q] * rng;
            }
            float outv = base + offv;
            if (!isfinite(outv)) outv = 0.0f;
            o[j] = outv;
        }
        ov[idx] = make_float4(o[0], o[1], o[2], o[3]);
    }
}

// ---------------------------------------------------------------------------
// Launch
// ---------------------------------------------------------------------------
extern "C" void kernel_launch(void* const* d_in, const int* in_sizes, int n_in,
                              void* d_out, int out_size) {
    (void)in_sizes; (void)n_in; (void)out_size;
    const float* x    = (const float*)d_in[0];   // [4096, 1024]
    const float* W    = (const float*)d_in[1];   // [4096, 1024]
    const float* bias = (const float*)d_in[2];   // [4096]
    float* out = (float*)d_out;                  // [4096, 4096]

    cudaFuncSetAttribute(gemm_hmma, cudaFuncAttributeMaxDynamicSharedMemorySize, GEMM_SMEM);

    split_fp16<<<(2 * A_F4) / 1024, 256>>>(x, W);
    dim3 grid(OUT_N / 128, S_ROWS / 128);        // (32, 32)
    gemm_hmma<<<grid, 256, GEMM_SMEM>>>(bias);
    row_quant<<<S_ROWS, NTH>>>(out);
}